// round 10
// baseline (speedup 1.0000x reference)
#include <cuda_runtime.h>
#include <cuda_fp16.h>
#include <cstdint>
#include <math.h>

// Problem constants
#define T_TOK 16384
#define TK    32768
#define NE    8
#define CDIM  1024
#define INTER 2730
#define N2    5460
#define CAP   2560
#define AST   2752
#define NP    2752
#define KP    2752

typedef unsigned short ushort_t;

// ---------------- scratch ----------------
__device__ unsigned long long g_key[TK];
__device__ int   g_eid[TK];
__device__ float g_val[TK];
__device__ unsigned long long g_thresh[NE];
__device__ int   g_cnt[NE];
__device__ int   g_tok[NE][CAP];
__device__ float g_w[NE][CAP];

__device__ ushort_t g_x16[(size_t)T_TOK * CDIM];
__device__ ushort_t g_wg[(size_t)NE * NP * CDIM];
__device__ ushort_t g_wu[(size_t)NE * NP * CDIM];
__device__ ushort_t g_wd[(size_t)NE * CDIM * KP];
__device__ ushort_t g_act[(size_t)NE * CAP * AST];

// ---------------- helpers ----------------
__device__ __forceinline__ ushort_t f2h(float f) {
    __half h = __float2half_rn(f);
    return *(ushort_t*)&h;
}
__device__ __forceinline__ uint32_t saddr(const void* p) {
    return (uint32_t)__cvta_generic_to_shared(p);
}
__device__ __forceinline__ void ldsm4(uint32_t* r, uint32_t a) {
    asm volatile("ldmatrix.sync.aligned.m8n8.x4.shared.b16 {%0,%1,%2,%3}, [%4];"
                 : "=r"(r[0]), "=r"(r[1]), "=r"(r[2]), "=r"(r[3]) : "r"(a));
}
__device__ __forceinline__ void mma16(float* c, const uint32_t* a, const uint32_t* b) {
    asm volatile(
        "mma.sync.aligned.m16n8k16.row.col.f32.f16.f16.f32 "
        "{%0,%1,%2,%3},{%4,%5,%6,%7},{%8,%9},{%0,%1,%2,%3};"
        : "+f"(c[0]), "+f"(c[1]), "+f"(c[2]), "+f"(c[3])
        : "r"(a[0]), "r"(a[1]), "r"(a[2]), "r"(a[3]), "r"(b[0]), "r"(b[1]));
}
__device__ __forceinline__ void mbar_init(uint32_t mb) {
    asm volatile("mbarrier.init.shared.b64 [%0], %1;" :: "r"(mb), "r"(1u) : "memory");
}
__device__ __forceinline__ void mbar_expect(uint32_t mb, uint32_t bytes) {
    asm volatile("mbarrier.arrive.expect_tx.shared.b64 _, [%0], %1;"
                 :: "r"(mb), "r"(bytes) : "memory");
}
__device__ __forceinline__ void mbar_wait(uint32_t mb, uint32_t parity) {
    asm volatile(
        "{\n\t.reg .pred P;\n\tWAIT_%=:\n\t"
        "mbarrier.try_wait.parity.acquire.cta.shared::cta.b64 P, [%0], %1, 0x989680;\n\t"
        "@P bra.uni DONE_%=;\n\tbra.uni WAIT_%=;\n\tDONE_%=:\n\t}"
        :: "r"(mb), "r"(parity) : "memory");
}
__device__ __forceinline__ void bulk_cp(uint32_t dst, const void* src,
                                        uint32_t bytes, uint32_t mb) {
    asm volatile(
        "cp.async.bulk.shared::cta.global.mbarrier::complete_tx::bytes [%0], [%1], %2, [%3];"
        :: "r"(dst), "l"(src), "r"(bytes), "r"(mb) : "memory");
}

// ================== fused prep kernel: block-role dispatch ==================
// roles: [0, NB_GU): gate_up transpose | [NB_GU, +NB_DW): down transpose
//        | +NB_X: x->fp16 | +NB_GATE: gating | +NB_ZERO: out zero + init
#define NB_GU   (171 * 32 * 8)   // 43776
#define NB_DW   (32 * 86 * 8)    // 22016
#define NB_X    2048
#define NB_GATE 2048
#define NB_ZERO 1024
#define NB_TOT  (NB_GU + NB_DW + NB_X + NB_GATE + NB_ZERO)

__global__ __launch_bounds__(256) void kprep(
    const float* __restrict__ x, const float* __restrict__ cond,
    const float* __restrict__ snr, const float* __restrict__ gw,
    const float* __restrict__ wgu, const float* __restrict__ wd,
    float* __restrict__ out, int out_size)
{
    __shared__ float tile[32][33];
    const int bid = blockIdx.x;
    const int tid = threadIdx.x;

    if (bid < NB_GU) {
        // ---- transpose gate_up_w [e][k][5460] -> fp16 [e][n][k] ----
        int b = bid;
        int n0 = (b % 171) * 32;
        int k0b = ((b / 171) % 32) * 32;
        int e = b / (171 * 32);
        int tx = tid & 31, ty = tid >> 5;
        for (int i = ty; i < 32; i += 8) {
            int n = n0 + tx, k = k0b + i;
            tile[i][tx] = (n < N2) ? wgu[((size_t)e * CDIM + k) * N2 + n] : 0.0f;
        }
        __syncthreads();
        for (int i = ty; i < 32; i += 8) {
            int n = n0 + i, k = k0b + tx;
            if (n >= N2) continue;
            ushort_t h = f2h(tile[tx][i]);
            if (n < INTER) g_wg[((size_t)e * NP + n) * CDIM + k] = h;
            else           g_wu[((size_t)e * NP + (n - INTER)) * CDIM + k] = h;
        }
        return;
    }
    if (bid < NB_GU + NB_DW) {
        // ---- transpose down_w [e][k=INTER][n=CDIM] -> fp16 [e][n][k] ----
        int b = bid - NB_GU;
        int n0 = (b % 32) * 32;
        int k0b = ((b / 32) % 86) * 32;
        int e = b / (32 * 86);
        int tx = tid & 31, ty = tid >> 5;
        for (int i = ty; i < 32; i += 8) {
            int k = k0b + i;
            tile[i][tx] = (k < INTER) ? wd[((size_t)e * INTER + k) * CDIM + n0 + tx] : 0.0f;
        }
        __syncthreads();
        for (int i = ty; i < 32; i += 8) {
            int n = n0 + i, k = k0b + tx;
            if (k >= INTER) continue;
            g_wd[((size_t)e * CDIM + n) * KP + k] = f2h(tile[tx][i]);
        }
        return;
    }
    if (bid < NB_GU + NB_DW + NB_X) {
        // ---- x -> fp16 ----
        int b = bid - NB_GU - NB_DW;
        const int n = T_TOK * CDIM;
        int i = b * 256 + tid;
        int stride = NB_X * 256;
        for (int j = i * 4; j < n; j += stride * 4) {
            float4 v = *(const float4*)(x + j);
            float* pv = (float*)&v;
#pragma unroll
            for (int p = 0; p < 2; ++p) {
                ushort_t h0 = f2h(pv[2*p]);
                ushort_t h1 = f2h(pv[2*p+1]);
                *(uint32_t*)(g_x16 + j + 2*p) = (uint32_t)h0 | ((uint32_t)h1 << 16);
            }
        }
        return;
    }
    if (bid < NB_GU + NB_DW + NB_X + NB_GATE) {
        // ---- gating: one warp per token ----
        int b = bid - NB_GU - NB_DW - NB_X;
        int warp = b * 8 + (tid >> 5);
        int lane = tid & 31;
        int t = warp;
        int bb = t >> 12;

        float acc[NE];
#pragma unroll
        for (int e = 0; e < NE; ++e) acc[e] = 0.0f;

        const float* xr = x + (size_t)t * CDIM;
        const float* cr = cond + (size_t)bb * CDIM;
        for (int d = lane; d < 2 * CDIM; d += 32) {
            float v = (d < CDIM) ? xr[d] : cr[d - CDIM];
            const float* wrow = gw + (size_t)d * NE;
#pragma unroll
            for (int e = 0; e < NE; ++e) acc[e] += v * wrow[e];
        }
#pragma unroll
        for (int e = 0; e < NE; ++e) {
#pragma unroll
            for (int o = 16; o > 0; o >>= 1)
                acc[e] += __shfl_xor_sync(0xFFFFFFFFu, acc[e], o);
        }

        if (lane == 0) {
            bool hn = snr[bb] < 0.5f;
            float lg[NE];
#pragma unroll
            for (int e = 0; e < NE; ++e)
                lg[e] = (hn && e >= 2) ? -INFINITY : acc[e];

            float mx = lg[0];
#pragma unroll
            for (int e = 1; e < NE; ++e) mx = fmaxf(mx, lg[e]);
            float p[NE], s = 0.0f;
#pragma unroll
            for (int e = 0; e < NE; ++e) { p[e] = expf(lg[e] - mx); s += p[e]; }
            float inv = 1.0f / s;
#pragma unroll
            for (int e = 0; e < NE; ++e) p[e] *= inv;

            int i0 = 0; float p0 = p[0];
#pragma unroll
            for (int e = 1; e < NE; ++e) if (p[e] > p0) { p0 = p[e]; i0 = e; }
            int i1 = -1; float p1 = -1.0f;
#pragma unroll
            for (int e = 0; e < NE; ++e) if (e != i0 && p[e] > p1) { p1 = p[e]; i1 = e; }

            float denom = fmaxf(p0 + p1, 1e-12f);
            float w0 = p0 / denom, w1 = p1 / denom;

            int s0 = t * 2, s1 = t * 2 + 1;
            g_eid[s0] = i0; g_val[s0] = w0;
            g_key[s0] = ((unsigned long long)__float_as_uint(w0) << 32) |
                        (unsigned long long)(0xFFFFFFFFu - (unsigned)s0);
            g_eid[s1] = i1; g_val[s1] = w1;
            g_key[s1] = ((unsigned long long)__float_as_uint(w1) << 32) |
                        (unsigned long long)(0xFFFFFFFFu - (unsigned)s1);
        }
        return;
    }
    {
        // ---- zero out + init routing state ----
        int b = bid - NB_GU - NB_DW - NB_X - NB_GATE;
        int i = b * 256 + tid;
        int stride = NB_ZERO * 256;
        for (int j = i; j < out_size; j += stride) out[j] = 0.0f;
        if (i < NE) g_cnt[i] = 0;
        for (int j = i; j < NE * CAP; j += stride) {
            ((int*)g_tok)[j] = 0;
            ((float*)g_w)[j] = 0.0f;
        }
    }
}

// ---------------- kernel 2: per-expert exact radix select ----------------
__global__ void k2_select() {
    int e = blockIdx.x;
    int tid = threadIdx.x;
    __shared__ int hist[256];
    __shared__ unsigned long long sh_prefix;
    __shared__ int sh_rem;
    __shared__ int sh_n;

    int cnt = 0;
    for (int s = tid; s < TK; s += 256) if (g_eid[s] == e) cnt++;
    if (tid == 0) sh_n = 0;
    __syncthreads();
    atomicAdd(&sh_n, cnt);
    __syncthreads();
    int n = sh_n;

    if (n <= CAP) {
        if (tid == 0) g_thresh[e] = 0ULL;
        return;
    }

    if (tid == 0) { sh_prefix = 0ULL; sh_rem = CAP; }
    __syncthreads();

    for (int p = 7; p >= 0; --p) {
        if (tid < 256) hist[tid] = 0;
        __syncthreads();
        unsigned long long prefix = sh_prefix;
        int shift_lo = p * 8;
        for (int s = tid; s < TK; s += 256) {
            if (g_eid[s] != e) continue;
            unsigned long long key = g_key[s];
            bool match = (p == 7) || (((key ^ prefix) >> ((p + 1) * 8)) == 0ULL);
            if (match)
                atomicAdd(&hist[(int)((key >> shift_lo) & 255ULL)], 1);
        }
        __syncthreads();
        if (tid == 0) {
            int rem = sh_rem;
            int cum = 0, d = 255;
            for (; d > 0; --d) { cum += hist[d]; if (cum >= rem) break; }
            if (cum < rem) cum += hist[0];
            sh_prefix |= ((unsigned long long)d) << shift_lo;
            sh_rem = rem - (cum - hist[d]);
        }
        __syncthreads();
    }
    if (tid == 0) g_thresh[e] = sh_prefix;
}

// ---------------- kernel 3: compaction ----------------
__global__ void k3_compact() {
    int s = blockIdx.x * blockDim.x + threadIdx.x;
    if (s >= TK) return;
    int e = g_eid[s];
    if (g_key[s] >= g_thresh[e]) {
        int pos = atomicAdd(&g_cnt[e], 1);
        if (pos < CAP) {
            g_tok[e][pos] = s >> 1;
            g_w[e][pos] = g_val[s];
        }
    }
}

// ======== GEMM kernels: BK=64, 3-stage bulk pipeline, fill-at-top ==========
#define RS2 144

// ---------------- kernel 4: gate_up GEMM (fp16) + SiLU*up -------------------
#define K4_STG   (256 * RS2)    // 36864
#define K4_BYTES (256 * 128)
__global__ __launch_bounds__(256, 2) void k4_gemm1() {
    extern __shared__ char sm[];
    const uint32_t base = saddr(sm);
    const uint32_t mb0 = base;          // three mbarriers @0,8,16
    const uint32_t tiles = base + 32;
    const int e = blockIdx.z, m0 = blockIdx.x * 128, n0 = blockIdx.y * 64;
    const int tid = threadIdx.x, warp = tid >> 5, lane = tid & 31;
    const int wm = warp >> 1, wn = warp & 1;
    const int gID = lane >> 2, t4 = lane & 3;

    if (tid == 0) { mbar_init(mb0); mbar_init(mb0 + 8); mbar_init(mb0 + 16); }

    const ushort_t* srcRow;
    if (tid < 128) {
        int tok = g_tok[e][m0 + tid];
        srcRow = g_x16 + (size_t)tok * CDIM;
    } else {
        int r = tid - 128;
        srcRow = (r < 64)
            ? g_wg + ((size_t)e * NP + n0 + r) * CDIM
            : g_wu + ((size_t)e * NP + n0 + (r - 64)) * CDIM;
    }
    const uint32_t dstOff = tiles + (uint32_t)tid * RS2;
    __syncthreads();

    auto fill = [&](int it) {
        int s = it % 3;
        if (tid == 0) mbar_expect(mb0 + s * 8, K4_BYTES);
        bulk_cp(dstOff + s * K4_STG, srcRow + it * 64, 128, mb0 + s * 8);
    };

    const uint32_t aoffr = (uint32_t)((wm * 32 + (lane & 15)) * RS2 + (lane >> 4) * 16);
    const uint32_t boffr = (uint32_t)(128 * RS2 +
                            ((lane & 7) + ((lane >> 4) & 1) * 8) * RS2 +
                            ((lane >> 3) & 1) * 16);

    float acc[2][2][4][4] = {};

    const int NIT = CDIM / 64;   // 16
    fill(0); fill(1);

#pragma unroll 1
    for (int it = 0; it < NIT; ++it) {
        mbar_wait(mb0 + (it % 3) * 8, (uint32_t)((it / 3) & 1));
        if (it + 2 < NIT) fill(it + 2);   // buffer (it+2)%3 free since iter it-1
        const uint32_t s = tiles + (it % 3) * K4_STG;
#pragma unroll
        for (int ks = 0; ks < 4; ++ks) {
            uint32_t ah[2][4], bb[2][2][4];
#pragma unroll
            for (int mt = 0; mt < 2; ++mt)
                ldsm4(ah[mt], s + aoffr + mt * 16 * RS2 + ks * 32);
#pragma unroll
            for (int g = 0; g < 2; ++g)
#pragma unroll
                for (int np = 0; np < 2; ++np)
                    ldsm4(bb[g][np], s + boffr + (g * 64 + wn * 32 + np * 16) * RS2 + ks * 32);
#pragma unroll
            for (int g = 0; g < 2; ++g)
#pragma unroll
                for (int mt = 0; mt < 2; ++mt)
#pragma unroll
                    for (int nt = 0; nt < 4; ++nt) {
                        const uint32_t* bp = &bb[g][nt >> 1][(nt & 1) * 2];
                        mma16(acc[g][mt][nt], ah[mt], bp);
                    }
        }
        __syncthreads();
    }

    // epilogue: silu(g)*u -> fp16
    ushort_t* pa = g_act + (size_t)e * CAP * AST;
#pragma unroll
    for (int mt = 0; mt < 2; ++mt)
#pragma unroll
        for (int nt = 0; nt < 4; ++nt) {
            int rbase = m0 + wm * 32 + mt * 16 + gID;
            int col = n0 + wn * 32 + nt * 8 + 2 * t4;
            if (col >= INTER) continue;
#pragma unroll
            for (int rq = 0; rq < 2; ++rq) {
                int row = rbase + rq * 8;
                float g0 = acc[0][mt][nt][rq * 2],     u0 = acc[1][mt][nt][rq * 2];
                float g1 = acc[0][mt][nt][rq * 2 + 1], u1 = acc[1][mt][nt][rq * 2 + 1];
                float a0 = __fdividef(g0, 1.0f + __expf(-g0)) * u0;
                float a1 = __fdividef(g1, 1.0f + __expf(-g1)) * u1;
                ushort_t h0 = f2h(a0), h1 = f2h(a1);
                *(uint32_t*)(pa + (size_t)row * AST + col) = (uint32_t)h0 | ((uint32_t)h1 << 16);
            }
        }
}

// ---------------- kernel 5: down GEMM (fp16) + scatter ----------------------
#define K5_STG   (192 * RS2)    // 27648
#define K5_BYTES (192 * 128)
__global__ __launch_bounds__(256, 2) void k5_gemm2(float* __restrict__ out) {
    extern __shared__ char sm[];
    const uint32_t base = saddr(sm);
    const uint32_t mb0 = base;
    const uint32_t tiles = base + 32;
    const int e = blockIdx.z, m0 = blockIdx.x * 128, n0 = blockIdx.y * 64;
    const int tid = threadIdx.x, warp = tid >> 5, lane = tid & 31;
    const int wm = warp >> 1, wn = warp & 1;
    const int gID = lane >> 2, t4 = lane & 3;

    if (tid == 0) { mbar_init(mb0); mbar_init(mb0 + 8); mbar_init(mb0 + 16); }

    const ushort_t* srcRow = nullptr;
    if (tid < 128) {
        srcRow = g_act + ((size_t)e * CAP + m0 + tid) * AST;
    } else if (tid < 192) {
        srcRow = g_wd + ((size_t)e * CDIM + n0 + (tid - 128)) * KP;
    }
    const uint32_t dstOff = tiles + (uint32_t)tid * RS2;
    __syncthreads();

    auto fill = [&](int it) {
        int s = it % 3;
        if (tid == 0) mbar_expect(mb0 + s * 8, K5_BYTES);
        if (tid < 192) bulk_cp(dstOff + s * K5_STG, srcRow + it * 64, 128, mb0 + s * 8);
    };

    const uint32_t aoffr = (uint32_t)((wm * 32 + (lane & 15)) * RS2 + (lane >> 4) * 16);
    const uint32_t boffr = (uint32_t)(128 * RS2 +
                            ((lane & 7) + ((lane >> 4) & 1) * 8) * RS2 +
                            ((lane >> 3) & 1) * 16);

    float acc[2][4][4] = {};

    const int NIT = KP / 64;   // 43
    fill(0); fill(1);

#pragma unroll 1
    for (int it = 0; it < NIT; ++it) {
        mbar_wait(mb0 + (it % 3) * 8, (uint32_t)((it / 3) & 1));
        if (it + 2 < NIT) fill(it + 2);
        const uint32_t s = tiles + (it % 3) * K5_STG;
#pragma unroll
        for (int ks = 0; ks < 4; ++ks) {
            uint32_t ah[2][4], bb[2][4];
#pragma unroll
            for (int mt = 0; mt < 2; ++mt)
                ldsm4(ah[mt], s + aoffr + mt * 16 * RS2 + ks * 32);
#pragma unroll
            for (int np = 0; np < 2; ++np)
                ldsm4(bb[np], s + boffr + (wn * 32 + np * 16) * RS2 + ks * 32);
#pragma unroll
            for (int mt = 0; mt < 2; ++mt)
#pragma unroll
                for (int nt = 0; nt < 4; ++nt) {
                    const uint32_t* bp = &bb[nt >> 1][(nt & 1) * 2];
                    mma16(acc[mt][nt], ah[mt], bp);
                }
        }
        __syncthreads();
    }

    // epilogue: scale by routing weight, atomic scatter
#pragma unroll
    for (int mt = 0; mt < 2; ++mt)
#pragma unroll
        for (int rq = 0; rq < 2; ++rq) {
            int row = m0 + wm * 32 + mt * 16 + gID + rq * 8;
            float w = g_w[e][row];
            if (w == 0.0f) continue;
            int tok = g_tok[e][row];
            float* orow = out + (size_t)tok * CDIM;
#pragma unroll
            for (int nt = 0; nt < 4; ++nt) {
                int col = n0 + wn * 32 + nt * 8 + 2 * t4;
                atomicAdd(&orow[col],     acc[mt][nt][rq * 2 + 0] * w);
                atomicAdd(&orow[col + 1], acc[mt][nt][rq * 2 + 1] * w);
            }
        }
}

// ---------------- launch ----------------
extern "C" void kernel_launch(void* const* d_in, const int* in_sizes, int n_in,
                              void* d_out, int out_size) {
    const float* x    = (const float*)d_in[0];
    const float* cond = (const float*)d_in[1];
    const float* snr  = (const float*)d_in[2];
    const float* gw   = (const float*)d_in[3];
    const float* wgu  = (const float*)d_in[4];
    const float* wd   = (const float*)d_in[5];
    float* out = (float*)d_out;

    const int SM4 = 32 + 3 * K4_STG;   // 110624
    const int SM5 = 32 + 3 * K5_STG;   // 82976
    cudaFuncSetAttribute(k4_gemm1, cudaFuncAttributeMaxDynamicSharedMemorySize, SM4);
    cudaFuncSetAttribute(k5_gemm2, cudaFuncAttributeMaxDynamicSharedMemorySize, SM5);

    kprep<<<NB_TOT, 256>>>(x, cond, snr, gw, wgu, wd, out, out_size);
    k2_select<<<NE, 256>>>();
    k3_compact<<<TK / 256, 256>>>();

    dim3 gg1(CAP / 128, NP / 64, NE);    // 20 x 43 x 8
    k4_gemm1<<<gg1, 256, SM4>>>();

    dim3 gg2(CAP / 128, CDIM / 64, NE);  // 20 x 16 x 8
    k5_gemm2<<<gg2, 256, SM5>>>(out);
}

// round 11
// speedup vs baseline: 1.1516x; 1.1516x over previous
#include <cuda_runtime.h>
#include <cuda_fp16.h>
#include <cstdint>
#include <math.h>

// Problem constants
#define T_TOK 16384
#define TK    32768
#define NE    8
#define CDIM  1024
#define INTER 2730
#define N2    5460
#define CAP   2560
#define AST   2752
#define NP    2752
#define KP    2752

typedef unsigned short ushort_t;

// ---------------- scratch ----------------
__device__ unsigned long long g_key[TK];
__device__ int   g_eid[TK];
__device__ float g_val[TK];
__device__ unsigned long long g_thresh[NE];
__device__ int   g_cnt[NE];
__device__ int   g_tok[NE][CAP];
__device__ float g_w[NE][CAP];

__device__ ushort_t g_x16[(size_t)T_TOK * CDIM];
__device__ ushort_t g_wg[(size_t)NE * NP * CDIM];
__device__ ushort_t g_wu[(size_t)NE * NP * CDIM];
__device__ ushort_t g_wd[(size_t)NE * CDIM * KP];
__device__ ushort_t g_act[(size_t)NE * CAP * AST];

// ---------------- helpers ----------------
__device__ __forceinline__ ushort_t f2h(float f) {
    __half h = __float2half_rn(f);
    return *(ushort_t*)&h;
}
__device__ __forceinline__ uint32_t saddr(const void* p) {
    return (uint32_t)__cvta_generic_to_shared(p);
}
__device__ __forceinline__ void ldsm4(uint32_t* r, uint32_t a) {
    asm volatile("ldmatrix.sync.aligned.m8n8.x4.shared.b16 {%0,%1,%2,%3}, [%4];"
                 : "=r"(r[0]), "=r"(r[1]), "=r"(r[2]), "=r"(r[3]) : "r"(a));
}
__device__ __forceinline__ void mma16(float* c, const uint32_t* a, const uint32_t* b) {
    asm volatile(
        "mma.sync.aligned.m16n8k16.row.col.f32.f16.f16.f32 "
        "{%0,%1,%2,%3},{%4,%5,%6,%7},{%8,%9},{%0,%1,%2,%3};"
        : "+f"(c[0]), "+f"(c[1]), "+f"(c[2]), "+f"(c[3])
        : "r"(a[0]), "r"(a[1]), "r"(a[2]), "r"(a[3]), "r"(b[0]), "r"(b[1]));
}
__device__ __forceinline__ void mbar_init(uint32_t mb) {
    asm volatile("mbarrier.init.shared.b64 [%0], %1;" :: "r"(mb), "r"(1u) : "memory");
}
__device__ __forceinline__ void mbar_expect(uint32_t mb, uint32_t bytes) {
    asm volatile("mbarrier.arrive.expect_tx.shared.b64 _, [%0], %1;"
                 :: "r"(mb), "r"(bytes) : "memory");
}
__device__ __forceinline__ void mbar_wait(uint32_t mb, uint32_t parity) {
    asm volatile(
        "{\n\t.reg .pred P;\n\tWAIT_%=:\n\t"
        "mbarrier.try_wait.parity.acquire.cta.shared::cta.b64 P, [%0], %1, 0x989680;\n\t"
        "@P bra.uni DONE_%=;\n\tbra.uni WAIT_%=;\n\tDONE_%=:\n\t}"
        :: "r"(mb), "r"(parity) : "memory");
}
__device__ __forceinline__ void bulk_cp(uint32_t dst, const void* src,
                                        uint32_t bytes, uint32_t mb) {
    asm volatile(
        "cp.async.bulk.shared::cta.global.mbarrier::complete_tx::bytes [%0], [%1], %2, [%3];"
        :: "r"(dst), "l"(src), "r"(bytes), "r"(mb) : "memory");
}

// ================== fused prep kernel: block-role dispatch ==================
#define NB_GU   (171 * 32 * 8)   // 43776
#define NB_DW   (32 * 86 * 8)    // 22016
#define NB_X    2048
#define NB_GATE 2048
#define NB_ZERO 1024
#define NB_TOT  (NB_GU + NB_DW + NB_X + NB_GATE + NB_ZERO)

__global__ __launch_bounds__(256) void kprep(
    const float* __restrict__ x, const float* __restrict__ cond,
    const float* __restrict__ snr, const float* __restrict__ gw,
    const float* __restrict__ wgu, const float* __restrict__ wd,
    float* __restrict__ out, int out_size)
{
    __shared__ float tile[32][33];
    const int bid = blockIdx.x;
    const int tid = threadIdx.x;

    if (bid < NB_GU) {
        // ---- transpose gate_up_w [e][k][5460] -> fp16 [e][n][k] ----
        int b = bid;
        int n0 = (b % 171) * 32;
        int k0b = ((b / 171) % 32) * 32;
        int e = b / (171 * 32);
        int tx = tid & 31, ty = tid >> 5;
        for (int i = ty; i < 32; i += 8) {
            int n = n0 + tx, k = k0b + i;
            tile[i][tx] = (n < N2) ? wgu[((size_t)e * CDIM + k) * N2 + n] : 0.0f;
        }
        __syncthreads();
        for (int i = ty; i < 32; i += 8) {
            int n = n0 + i, k = k0b + tx;
            if (n >= N2) continue;
            ushort_t h = f2h(tile[tx][i]);
            if (n < INTER) g_wg[((size_t)e * NP + n) * CDIM + k] = h;
            else           g_wu[((size_t)e * NP + (n - INTER)) * CDIM + k] = h;
        }
        return;
    }
    if (bid < NB_GU + NB_DW) {
        // ---- transpose down_w [e][k=INTER][n=CDIM] -> fp16 [e][n][k] ----
        int b = bid - NB_GU;
        int n0 = (b % 32) * 32;
        int k0b = ((b / 32) % 86) * 32;
        int e = b / (32 * 86);
        int tx = tid & 31, ty = tid >> 5;
        for (int i = ty; i < 32; i += 8) {
            int k = k0b + i;
            tile[i][tx] = (k < INTER) ? wd[((size_t)e * INTER + k) * CDIM + n0 + tx] : 0.0f;
        }
        __syncthreads();
        for (int i = ty; i < 32; i += 8) {
            int n = n0 + i, k = k0b + tx;
            if (k >= INTER) continue;
            g_wd[((size_t)e * CDIM + n) * KP + k] = f2h(tile[tx][i]);
        }
        return;
    }
    if (bid < NB_GU + NB_DW + NB_X) {
        // ---- x -> fp16 ----
        int b = bid - NB_GU - NB_DW;
        const int n = T_TOK * CDIM;
        int i = b * 256 + tid;
        int stride = NB_X * 256;
        for (int j = i * 4; j < n; j += stride * 4) {
            float4 v = *(const float4*)(x + j);
            float* pv = (float*)&v;
#pragma unroll
            for (int p = 0; p < 2; ++p) {
                ushort_t h0 = f2h(pv[2*p]);
                ushort_t h1 = f2h(pv[2*p+1]);
                *(uint32_t*)(g_x16 + j + 2*p) = (uint32_t)h0 | ((uint32_t)h1 << 16);
            }
        }
        return;
    }
    if (bid < NB_GU + NB_DW + NB_X + NB_GATE) {
        // ---- gating: one warp per token ----
        int b = bid - NB_GU - NB_DW - NB_X;
        int warp = b * 8 + (tid >> 5);
        int lane = tid & 31;
        int t = warp;
        int bb = t >> 12;

        float acc[NE];
#pragma unroll
        for (int e = 0; e < NE; ++e) acc[e] = 0.0f;

        const float* xr = x + (size_t)t * CDIM;
        const float* cr = cond + (size_t)bb * CDIM;
        for (int d = lane; d < 2 * CDIM; d += 32) {
            float v = (d < CDIM) ? xr[d] : cr[d - CDIM];
            const float* wrow = gw + (size_t)d * NE;
#pragma unroll
            for (int e = 0; e < NE; ++e) acc[e] += v * wrow[e];
        }
#pragma unroll
        for (int e = 0; e < NE; ++e) {
#pragma unroll
            for (int o = 16; o > 0; o >>= 1)
                acc[e] += __shfl_xor_sync(0xFFFFFFFFu, acc[e], o);
        }

        if (lane == 0) {
            bool hn = snr[bb] < 0.5f;
            float lg[NE];
#pragma unroll
            for (int e = 0; e < NE; ++e)
                lg[e] = (hn && e >= 2) ? -INFINITY : acc[e];

            float mx = lg[0];
#pragma unroll
            for (int e = 1; e < NE; ++e) mx = fmaxf(mx, lg[e]);
            float p[NE], s = 0.0f;
#pragma unroll
            for (int e = 0; e < NE; ++e) { p[e] = expf(lg[e] - mx); s += p[e]; }
            float inv = 1.0f / s;
#pragma unroll
            for (int e = 0; e < NE; ++e) p[e] *= inv;

            int i0 = 0; float p0 = p[0];
#pragma unroll
            for (int e = 1; e < NE; ++e) if (p[e] > p0) { p0 = p[e]; i0 = e; }
            int i1 = -1; float p1 = -1.0f;
#pragma unroll
            for (int e = 0; e < NE; ++e) if (e != i0 && p[e] > p1) { p1 = p[e]; i1 = e; }

            float denom = fmaxf(p0 + p1, 1e-12f);
            float w0 = p0 / denom, w1 = p1 / denom;

            int s0 = t * 2, s1 = t * 2 + 1;
            g_eid[s0] = i0; g_val[s0] = w0;
            g_key[s0] = ((unsigned long long)__float_as_uint(w0) << 32) |
                        (unsigned long long)(0xFFFFFFFFu - (unsigned)s0);
            g_eid[s1] = i1; g_val[s1] = w1;
            g_key[s1] = ((unsigned long long)__float_as_uint(w1) << 32) |
                        (unsigned long long)(0xFFFFFFFFu - (unsigned)s1);
        }
        return;
    }
    {
        // ---- zero out + init routing state ----
        int b = bid - NB_GU - NB_DW - NB_X - NB_GATE;
        int i = b * 256 + tid;
        int stride = NB_ZERO * 256;
        for (int j = i; j < out_size; j += stride) out[j] = 0.0f;
        if (i < NE) g_cnt[i] = 0;
        for (int j = i; j < NE * CAP; j += stride) {
            ((int*)g_tok)[j] = 0;
            ((float*)g_w)[j] = 0.0f;
        }
    }
}

// ---------------- kernel 2: per-expert exact radix select ----------------
__global__ void k2_select() {
    int e = blockIdx.x;
    int tid = threadIdx.x;
    __shared__ int hist[256];
    __shared__ unsigned long long sh_prefix;
    __shared__ int sh_rem;
    __shared__ int sh_n;

    int cnt = 0;
    for (int s = tid; s < TK; s += 256) if (g_eid[s] == e) cnt++;
    if (tid == 0) sh_n = 0;
    __syncthreads();
    atomicAdd(&sh_n, cnt);
    __syncthreads();
    int n = sh_n;

    if (n <= CAP) {
        if (tid == 0) g_thresh[e] = 0ULL;
        return;
    }

    if (tid == 0) { sh_prefix = 0ULL; sh_rem = CAP; }
    __syncthreads();

    for (int p = 7; p >= 0; --p) {
        if (tid < 256) hist[tid] = 0;
        __syncthreads();
        unsigned long long prefix = sh_prefix;
        int shift_lo = p * 8;
        for (int s = tid; s < TK; s += 256) {
            if (g_eid[s] != e) continue;
            unsigned long long key = g_key[s];
            bool match = (p == 7) || (((key ^ prefix) >> ((p + 1) * 8)) == 0ULL);
            if (match)
                atomicAdd(&hist[(int)((key >> shift_lo) & 255ULL)], 1);
        }
        __syncthreads();
        if (tid == 0) {
            int rem = sh_rem;
            int cum = 0, d = 255;
            for (; d > 0; --d) { cum += hist[d]; if (cum >= rem) break; }
            if (cum < rem) cum += hist[0];
            sh_prefix |= ((unsigned long long)d) << shift_lo;
            sh_rem = rem - (cum - hist[d]);
        }
        __syncthreads();
    }
    if (tid == 0) g_thresh[e] = sh_prefix;
}

// ---------------- kernel 3: compaction ----------------
__global__ void k3_compact() {
    int s = blockIdx.x * blockDim.x + threadIdx.x;
    if (s >= TK) return;
    int e = g_eid[s];
    if (g_key[s] >= g_thresh[e]) {
        int pos = atomicAdd(&g_cnt[e], 1);
        if (pos < CAP) {
            g_tok[e][pos] = s >> 1;
            g_w[e][pos] = g_val[s];
        }
    }
}

// ======== GEMM kernels: BK=64, 2-stage bulk-copy pipeline, ldmatrix =========
#define RS2 144

// ---------------- kernel 4: gate_up GEMM (fp16) + SiLU*up -------------------
#define K4_STG   (256 * RS2)    // 36864
#define K4_BYTES (256 * 128)
__global__ __launch_bounds__(256) void k4_gemm1() {
    extern __shared__ char sm[];
    const uint32_t base = saddr(sm);
    const uint32_t mb0 = base;          // two mbarriers @0, @8
    const uint32_t tiles = base + 16;
    const int e = blockIdx.z, m0 = blockIdx.x * 128, n0 = blockIdx.y * 64;
    const int tid = threadIdx.x, warp = tid >> 5, lane = tid & 31;
    const int wm = warp >> 1, wn = warp & 1;
    const int gID = lane >> 2, t4 = lane & 3;

    if (tid == 0) { mbar_init(mb0); mbar_init(mb0 + 8); }

    const ushort_t* srcRow;
    if (tid < 128) {
        int tok = g_tok[e][m0 + tid];
        srcRow = g_x16 + (size_t)tok * CDIM;
    } else {
        int r = tid - 128;
        srcRow = (r < 64)
            ? g_wg + ((size_t)e * NP + n0 + r) * CDIM
            : g_wu + ((size_t)e * NP + n0 + (r - 64)) * CDIM;
    }
    const uint32_t dstOff = tiles + (uint32_t)tid * RS2;
    __syncthreads();

    auto fill = [&](int it) {
        int s = it & 1;
        if (tid == 0) mbar_expect(mb0 + s * 8, K4_BYTES);
        bulk_cp(dstOff + s * K4_STG, srcRow + it * 64, 128, mb0 + s * 8);
    };

    const uint32_t aoffr = (uint32_t)((wm * 32 + (lane & 15)) * RS2 + (lane >> 4) * 16);
    const uint32_t boffr = (uint32_t)(128 * RS2 +
                            ((lane & 7) + ((lane >> 4) & 1) * 8) * RS2 +
                            ((lane >> 3) & 1) * 16);

    float acc[2][2][4][4] = {};

    const int NIT = CDIM / 64;   // 16
    fill(0); fill(1);

#pragma unroll 1
    for (int it = 0; it < NIT; ++it) {
        mbar_wait(mb0 + (it & 1) * 8, (uint32_t)((it >> 1) & 1));
        const uint32_t s = tiles + (it & 1) * K4_STG;
#pragma unroll
        for (int ks = 0; ks < 4; ++ks) {
            uint32_t ah[2][4], bb[2][2][4];
#pragma unroll
            for (int mt = 0; mt < 2; ++mt)
                ldsm4(ah[mt], s + aoffr + mt * 16 * RS2 + ks * 32);
#pragma unroll
            for (int g = 0; g < 2; ++g)
#pragma unroll
                for (int np = 0; np < 2; ++np)
                    ldsm4(bb[g][np], s + boffr + (g * 64 + wn * 32 + np * 16) * RS2 + ks * 32);
#pragma unroll
            for (int g = 0; g < 2; ++g)
#pragma unroll
                for (int mt = 0; mt < 2; ++mt)
#pragma unroll
                    for (int nt = 0; nt < 4; ++nt) {
                        const uint32_t* bp = &bb[g][nt >> 1][(nt & 1) * 2];
                        mma16(acc[g][mt][nt], ah[mt], bp);
                    }
        }
        __syncthreads();
        if (it + 2 < NIT) fill(it + 2);
    }

    // epilogue: silu(g)*u -> fp16
    ushort_t* pa = g_act + (size_t)e * CAP * AST;
#pragma unroll
    for (int mt = 0; mt < 2; ++mt)
#pragma unroll
        for (int nt = 0; nt < 4; ++nt) {
            int rbase = m0 + wm * 32 + mt * 16 + gID;
            int col = n0 + wn * 32 + nt * 8 + 2 * t4;
            if (col >= INTER) continue;
#pragma unroll
            for (int rq = 0; rq < 2; ++rq) {
                int row = rbase + rq * 8;
                float g0 = acc[0][mt][nt][rq * 2],     u0 = acc[1][mt][nt][rq * 2];
                float g1 = acc[0][mt][nt][rq * 2 + 1], u1 = acc[1][mt][nt][rq * 2 + 1];
                float a0 = __fdividef(g0, 1.0f + __expf(-g0)) * u0;
                float a1 = __fdividef(g1, 1.0f + __expf(-g1)) * u1;
                ushort_t h0 = f2h(a0), h1 = f2h(a1);
                *(uint32_t*)(pa + (size_t)row * AST + col) = (uint32_t)h0 | ((uint32_t)h1 << 16);
            }
        }
}

// ---------------- kernel 5: down GEMM (fp16) + scatter ----------------------
#define K5_STG   (192 * RS2)    // 27648
#define K5_BYTES (192 * 128)
__global__ __launch_bounds__(256) void k5_gemm2(float* __restrict__ out) {
    extern __shared__ char sm[];
    const uint32_t base = saddr(sm);
    const uint32_t mb0 = base;
    const uint32_t tiles = base + 16;
    const int e = blockIdx.z, m0 = blockIdx.x * 128, n0 = blockIdx.y * 64;
    const int tid = threadIdx.x, warp = tid >> 5, lane = tid & 31;
    const int wm = warp >> 1, wn = warp & 1;
    const int gID = lane >> 2, t4 = lane & 3;

    if (tid == 0) { mbar_init(mb0); mbar_init(mb0 + 8); }

    const ushort_t* srcRow = nullptr;
    if (tid < 128) {
        srcRow = g_act + ((size_t)e * CAP + m0 + tid) * AST;
    } else if (tid < 192) {
        srcRow = g_wd + ((size_t)e * CDIM + n0 + (tid - 128)) * KP;
    }
    const uint32_t dstOff = tiles + (uint32_t)tid * RS2;
    __syncthreads();

    auto fill = [&](int it) {
        int s = it & 1;
        if (tid == 0) mbar_expect(mb0 + s * 8, K5_BYTES);
        if (tid < 192) bulk_cp(dstOff + s * K5_STG, srcRow + it * 64, 128, mb0 + s * 8);
    };

    const uint32_t aoffr = (uint32_t)((wm * 32 + (lane & 15)) * RS2 + (lane >> 4) * 16);
    const uint32_t boffr = (uint32_t)(128 * RS2 +
                            ((lane & 7) + ((lane >> 4) & 1) * 8) * RS2 +
                            ((lane >> 3) & 1) * 16);

    float acc[2][4][4] = {};

    const int NIT = KP / 64;   // 43
    fill(0); fill(1);

#pragma unroll 1
    for (int it = 0; it < NIT; ++it) {
        mbar_wait(mb0 + (it & 1) * 8, (uint32_t)((it >> 1) & 1));
        const uint32_t s = tiles + (it & 1) * K5_STG;
#pragma unroll
        for (int ks = 0; ks < 4; ++ks) {
            uint32_t ah[2][4], bb[2][4];
#pragma unroll
            for (int mt = 0; mt < 2; ++mt)
                ldsm4(ah[mt], s + aoffr + mt * 16 * RS2 + ks * 32);
#pragma unroll
            for (int np = 0; np < 2; ++np)
                ldsm4(bb[np], s + boffr + (wn * 32 + np * 16) * RS2 + ks * 32);
#pragma unroll
            for (int mt = 0; mt < 2; ++mt)
#pragma unroll
                for (int nt = 0; nt < 4; ++nt) {
                    const uint32_t* bp = &bb[nt >> 1][(nt & 1) * 2];
                    mma16(acc[mt][nt], ah[mt], bp);
                }
        }
        __syncthreads();
        if (it + 2 < NIT) fill(it + 2);
    }

    // epilogue: scale by routing weight, atomic scatter
#pragma unroll
    for (int mt = 0; mt < 2; ++mt)
#pragma unroll
        for (int rq = 0; rq < 2; ++rq) {
            int row = m0 + wm * 32 + mt * 16 + gID + rq * 8;
            float w = g_w[e][row];
            if (w == 0.0f) continue;
            int tok = g_tok[e][row];
            float* orow = out + (size_t)tok * CDIM;
#pragma unroll
            for (int nt = 0; nt < 4; ++nt) {
                int col = n0 + wn * 32 + nt * 8 + 2 * t4;
                atomicAdd(&orow[col],     acc[mt][nt][rq * 2 + 0] * w);
                atomicAdd(&orow[col + 1], acc[mt][nt][rq * 2 + 1] * w);
            }
        }
}

// ---------------- launch ----------------
extern "C" void kernel_launch(void* const* d_in, const int* in_sizes, int n_in,
                              void* d_out, int out_size) {
    const float* x    = (const float*)d_in[0];
    const float* cond = (const float*)d_in[1];
    const float* snr  = (const float*)d_in[2];
    const float* gw   = (const float*)d_in[3];
    const float* wgu  = (const float*)d_in[4];
    const float* wd   = (const float*)d_in[5];
    float* out = (float*)d_out;

    const int SM4 = 16 + 2 * K4_STG;   // 73744
    const int SM5 = 16 + 2 * K5_STG;   // 55312
    cudaFuncSetAttribute(k4_gemm1, cudaFuncAttributeMaxDynamicSharedMemorySize, SM4);
    cudaFuncSetAttribute(k5_gemm2, cudaFuncAttributeMaxDynamicSharedMemorySize, SM5);

    kprep<<<NB_TOT, 256>>>(x, cond, snr, gw, wgu, wd, out, out_size);
    k2_select<<<NE, 256>>>();
    k3_compact<<<TK / 256, 256>>>();

    dim3 gg1(CAP / 128, NP / 64, NE);    // 20 x 43 x 8
    k4_gemm1<<<gg1, 256, SM4>>>();

    dim3 gg2(CAP / 128, CDIM / 64, NE);  // 20 x 16 x 8
    k5_gemm2<<<gg2, 256, SM5>>>(out);
}

// round 12
// speedup vs baseline: 1.4453x; 1.2550x over previous
#include <cuda_runtime.h>
#include <cuda_fp16.h>
#include <cstdint>
#include <math.h>

// Problem constants
#define T_TOK 16384
#define TK    32768
#define NE    8
#define CDIM  1024
#define INTER 2730
#define N2    5460
#define CAP   2560
#define NBT   43      // n-tiles for gate/up (2752/64) and k-tiles for down
#define KBT   16      // k-tiles over CDIM

typedef unsigned short ushort_t;

// ---------------- scratch ----------------
__device__ unsigned long long g_key[TK];
__device__ int   g_eid[TK];
__device__ float g_val[TK];
__device__ unsigned long long g_thresh[NE];
__device__ int   g_cnt[NE];
__device__ int   g_tok[NE][CAP];
__device__ float g_w[NE][CAP];

__device__ ushort_t g_x16[(size_t)T_TOK * CDIM];
// tiled, pre-swizzled operand storage (tile = 64 rows x 64 halves = 8192 B)
__device__ ushort_t g_wg[(size_t)NE * NBT * KBT * 4096];   // gate  [e][nb][kb]
__device__ ushort_t g_wu[(size_t)NE * NBT * KBT * 4096];   // up    [e][nb][kb]
__device__ ushort_t g_wd[(size_t)NE * KBT * NBT * 4096];   // down  [e][nb][kb]
__device__ ushort_t g_xt[(size_t)NE * KBT * CAP * 64];     // gathered A tiles [e][kb][m][64]
__device__ ushort_t g_act[(size_t)NE * NBT * CAP * 64];    // activations     [e][kb][m][64]

// ---------------- helpers ----------------
__device__ __forceinline__ ushort_t f2h(float f) {
    __half h = __float2half_rn(f);
    return *(ushort_t*)&h;
}
__device__ __forceinline__ uint32_t saddr(const void* p) {
    return (uint32_t)__cvta_generic_to_shared(p);
}
__device__ __forceinline__ void ldsm4(uint32_t* r, uint32_t a) {
    asm volatile("ldmatrix.sync.aligned.m8n8.x4.shared.b16 {%0,%1,%2,%3}, [%4];"
                 : "=r"(r[0]), "=r"(r[1]), "=r"(r[2]), "=r"(r[3]) : "r"(a));
}
__device__ __forceinline__ void mma16(float* c, const uint32_t* a, const uint32_t* b) {
    asm volatile(
        "mma.sync.aligned.m16n8k16.row.col.f32.f16.f16.f32 "
        "{%0,%1,%2,%3},{%4,%5,%6,%7},{%8,%9},{%0,%1,%2,%3};"
        : "+f"(c[0]), "+f"(c[1]), "+f"(c[2]), "+f"(c[3])
        : "r"(a[0]), "r"(a[1]), "r"(a[2]), "r"(a[3]), "r"(b[0]), "r"(b[1]));
}
__device__ __forceinline__ void mbar_init(uint32_t mb) {
    asm volatile("mbarrier.init.shared.b64 [%0], %1;" :: "r"(mb), "r"(1u) : "memory");
}
__device__ __forceinline__ void mbar_expect(uint32_t mb, uint32_t bytes) {
    asm volatile("mbarrier.arrive.expect_tx.shared.b64 _, [%0], %1;"
                 :: "r"(mb), "r"(bytes) : "memory");
}
__device__ __forceinline__ void mbar_wait(uint32_t mb, uint32_t parity) {
    asm volatile(
        "{\n\t.reg .pred P;\n\tWAIT_%=:\n\t"
        "mbarrier.try_wait.parity.acquire.cta.shared::cta.b64 P, [%0], %1, 0x989680;\n\t"
        "@P bra.uni DONE_%=;\n\tbra.uni WAIT_%=;\n\tDONE_%=:\n\t}"
        :: "r"(mb), "r"(parity) : "memory");
}
__device__ __forceinline__ void bulk_cp(uint32_t dst, const void* src,
                                        uint32_t bytes, uint32_t mb) {
    asm volatile(
        "cp.async.bulk.shared::cta.global.mbarrier::complete_tx::bytes [%0], [%1], %2, [%3];"
        :: "r"(dst), "l"(src), "r"(bytes), "r"(mb) : "memory");
}

// ================== fused prep kernel ==================
#define NB_GU   (171 * 32 * 8)   // 43776
#define NB_DW   (32 * 86 * 8)    // 22016
#define NB_X    2048
#define NB_GATE 2048
#define NB_ZERO 1024
#define NB_TOT  (NB_GU + NB_DW + NB_X + NB_GATE + NB_ZERO)

__global__ __launch_bounds__(256) void kprep(
    const float* __restrict__ x, const float* __restrict__ cond,
    const float* __restrict__ snr, const float* __restrict__ gw,
    const float* __restrict__ wgu, const float* __restrict__ wd,
    float* __restrict__ out, int out_size)
{
    __shared__ float tile[32][33];
    const int bid = blockIdx.x;
    const int tid = threadIdx.x;

    if (bid < NB_GU) {
        // gate_up transpose -> tiled swizzled fp16
        int b = bid;
        int n0 = (b % 171) * 32;
        int k0b = ((b / 171) % 32) * 32;
        int e = b / (171 * 32);
        int tx = tid & 31, ty = tid >> 5;
        for (int i = ty; i < 32; i += 8) {
            int n = n0 + tx, k = k0b + i;
            tile[i][tx] = (n < N2) ? wgu[((size_t)e * CDIM + k) * N2 + n] : 0.0f;
        }
        __syncthreads();
        for (int i = ty; i < 32; i += 8) {
            int n = n0 + i, k = k0b + tx;
            ushort_t h = f2h(tile[tx][i]);
            char* base;
            int nn;
            if (n < INTER) { base = (char*)g_wg; nn = n; }
            else           { base = (char*)g_wu; nn = n - INTER; }
            int nb = nn >> 6, nl = nn & 63, kb = k >> 6, kl = k & 63;
            size_t off = ((((size_t)e * NBT + nb) * KBT + kb) << 13)
                       + (size_t)(nl * 128 + ((kl * 2) ^ ((nl & 7) << 4)));
            *(ushort_t*)(base + off) = h;
        }
        return;
    }
    if (bid < NB_GU + NB_DW) {
        // down transpose -> tiled swizzled fp16 (zeros for k >= INTER)
        int b = bid - NB_GU;
        int n0 = (b % 32) * 32;
        int k0b = ((b / 32) % 86) * 32;
        int e = b / (32 * 86);
        int tx = tid & 31, ty = tid >> 5;
        for (int i = ty; i < 32; i += 8) {
            int k = k0b + i;
            tile[i][tx] = (k < INTER) ? wd[((size_t)e * INTER + k) * CDIM + n0 + tx] : 0.0f;
        }
        __syncthreads();
        for (int i = ty; i < 32; i += 8) {
            int n = n0 + i, k = k0b + tx;
            int nb = n >> 6, nl = n & 63, kb = k >> 6, kl = k & 63;
            size_t off = ((((size_t)e * KBT + nb) * NBT + kb) << 13)
                       + (size_t)(nl * 128 + ((kl * 2) ^ ((nl & 7) << 4)));
            *(ushort_t*)((char*)g_wd + off) = f2h(tile[tx][i]);
        }
        return;
    }
    if (bid < NB_GU + NB_DW + NB_X) {
        // x -> fp16
        int b = bid - NB_GU - NB_DW;
        const int n = T_TOK * CDIM;
        int i = b * 256 + tid;
        int stride = NB_X * 256;
        for (int j = i * 4; j < n; j += stride * 4) {
            float4 v = *(const float4*)(x + j);
            float* pv = (float*)&v;
#pragma unroll
            for (int p = 0; p < 2; ++p) {
                ushort_t h0 = f2h(pv[2*p]);
                ushort_t h1 = f2h(pv[2*p+1]);
                *(uint32_t*)(g_x16 + j + 2*p) = (uint32_t)h0 | ((uint32_t)h1 << 16);
            }
        }
        return;
    }
    if (bid < NB_GU + NB_DW + NB_X + NB_GATE) {
        // gating: one warp per token
        int b = bid - NB_GU - NB_DW - NB_X;
        int warp = b * 8 + (tid >> 5);
        int lane = tid & 31;
        int t = warp;
        int bb = t >> 12;

        float acc[NE];
#pragma unroll
        for (int e = 0; e < NE; ++e) acc[e] = 0.0f;

        const float* xr = x + (size_t)t * CDIM;
        const float* cr = cond + (size_t)bb * CDIM;
        for (int d = lane; d < 2 * CDIM; d += 32) {
            float v = (d < CDIM) ? xr[d] : cr[d - CDIM];
            const float* wrow = gw + (size_t)d * NE;
#pragma unroll
            for (int e = 0; e < NE; ++e) acc[e] += v * wrow[e];
        }
#pragma unroll
        for (int e = 0; e < NE; ++e) {
#pragma unroll
            for (int o = 16; o > 0; o >>= 1)
                acc[e] += __shfl_xor_sync(0xFFFFFFFFu, acc[e], o);
        }

        if (lane == 0) {
            bool hn = snr[bb] < 0.5f;
            float lg[NE];
#pragma unroll
            for (int e = 0; e < NE; ++e)
                lg[e] = (hn && e >= 2) ? -INFINITY : acc[e];

            float mx = lg[0];
#pragma unroll
            for (int e = 1; e < NE; ++e) mx = fmaxf(mx, lg[e]);
            float p[NE], s = 0.0f;
#pragma unroll
            for (int e = 0; e < NE; ++e) { p[e] = expf(lg[e] - mx); s += p[e]; }
            float inv = 1.0f / s;
#pragma unroll
            for (int e = 0; e < NE; ++e) p[e] *= inv;

            int i0 = 0; float p0 = p[0];
#pragma unroll
            for (int e = 1; e < NE; ++e) if (p[e] > p0) { p0 = p[e]; i0 = e; }
            int i1 = -1; float p1 = -1.0f;
#pragma unroll
            for (int e = 0; e < NE; ++e) if (e != i0 && p[e] > p1) { p1 = p[e]; i1 = e; }

            float denom = fmaxf(p0 + p1, 1e-12f);
            float w0 = p0 / denom, w1 = p1 / denom;

            int s0 = t * 2, s1 = t * 2 + 1;
            g_eid[s0] = i0; g_val[s0] = w0;
            g_key[s0] = ((unsigned long long)__float_as_uint(w0) << 32) |
                        (unsigned long long)(0xFFFFFFFFu - (unsigned)s0);
            g_eid[s1] = i1; g_val[s1] = w1;
            g_key[s1] = ((unsigned long long)__float_as_uint(w1) << 32) |
                        (unsigned long long)(0xFFFFFFFFu - (unsigned)s1);
        }
        return;
    }
    {
        // zero out + init routing state
        int b = bid - NB_GU - NB_DW - NB_X - NB_GATE;
        int i = b * 256 + tid;
        int stride = NB_ZERO * 256;
        for (int j = i; j < out_size; j += stride) out[j] = 0.0f;
        if (i < NE) g_cnt[i] = 0;
        for (int j = i; j < NE * CAP; j += stride) {
            ((int*)g_tok)[j] = 0;
            ((float*)g_w)[j] = 0.0f;
        }
    }
}

// ---------------- kernel 2: per-expert exact radix select ----------------
__global__ void k2_select() {
    int e = blockIdx.x;
    int tid = threadIdx.x;
    __shared__ int hist[256];
    __shared__ unsigned long long sh_prefix;
    __shared__ int sh_rem;
    __shared__ int sh_n;

    int cnt = 0;
    for (int s = tid; s < TK; s += 256) if (g_eid[s] == e) cnt++;
    if (tid == 0) sh_n = 0;
    __syncthreads();
    atomicAdd(&sh_n, cnt);
    __syncthreads();
    int n = sh_n;

    if (n <= CAP) {
        if (tid == 0) g_thresh[e] = 0ULL;
        return;
    }

    if (tid == 0) { sh_prefix = 0ULL; sh_rem = CAP; }
    __syncthreads();

    for (int p = 7; p >= 0; --p) {
        if (tid < 256) hist[tid] = 0;
        __syncthreads();
        unsigned long long prefix = sh_prefix;
        int shift_lo = p * 8;
        for (int s = tid; s < TK; s += 256) {
            if (g_eid[s] != e) continue;
            unsigned long long key = g_key[s];
            bool match = (p == 7) || (((key ^ prefix) >> ((p + 1) * 8)) == 0ULL);
            if (match)
                atomicAdd(&hist[(int)((key >> shift_lo) & 255ULL)], 1);
        }
        __syncthreads();
        if (tid == 0) {
            int rem = sh_rem;
            int cum = 0, d = 255;
            for (; d > 0; --d) { cum += hist[d]; if (cum >= rem) break; }
            if (cum < rem) cum += hist[0];
            sh_prefix |= ((unsigned long long)d) << shift_lo;
            sh_rem = rem - (cum - hist[d]);
        }
        __syncthreads();
    }
    if (tid == 0) g_thresh[e] = sh_prefix;
}

// ---------------- kernel 3: compaction ----------------
__global__ void k3_compact() {
    int s = blockIdx.x * blockDim.x + threadIdx.x;
    if (s >= TK) return;
    int e = g_eid[s];
    if (g_key[s] >= g_thresh[e]) {
        int pos = atomicAdd(&g_cnt[e], 1);
        if (pos < CAP) {
            g_tok[e][pos] = s >> 1;
            g_w[e][pos] = g_val[s];
        }
    }
}

// ---------------- kernel 3b: gather x rows into swizzled A tiles ------------
__global__ __launch_bounds__(256) void k3b_gather() {
    const int e = blockIdx.y;
    const int m = blockIdx.x * 8 + (threadIdx.x >> 5);
    const int lane = threadIdx.x & 31;
    const int tok = g_tok[e][m];
    const uint4* src = (const uint4*)(g_x16 + (size_t)tok * CDIM);
    char* dstb = (char*)g_xt + ((size_t)e * KBT * CAP) * 128;
    const uint32_t xr = (uint32_t)((m & 7) << 4);
#pragma unroll
    for (int q = 0; q < 4; ++q) {
        int c = lane + q * 32;               // 16B chunk index 0..127
        uint4 v = src[c];
        int kb = c >> 3;
        uint32_t cb = (uint32_t)((c & 7) * 16) ^ xr;
        *(uint4*)(dstb + ((size_t)kb * CAP + m) * 128 + cb) = v;
    }
}

// ======== GEMM kernels: tiled bulk-copy pipelines, swizzled smem ============

// ---------------- kernel 4: gate_up GEMM (fp16) + SiLU*up -------------------
#define K4_STG   32768          // A 16KB + Bg 8KB + Bu 8KB
#define K4_BYTES 32768
__global__ __launch_bounds__(256, 2) void k4_gemm1() {
    extern __shared__ char sm[];
    const uint32_t base = saddr(sm);
    const uint32_t mb0 = base;          // 3 mbarriers @0,8,16
    const uint32_t tiles = base + 128;
    const int e = blockIdx.z, m0 = blockIdx.x * 128, nb = blockIdx.y;
    const int tid = threadIdx.x, warp = tid >> 5, lane = tid & 31;
    const int wm = warp >> 1, wn = warp & 1;
    const int gID = lane >> 2, t4 = lane & 3;

    if (tid == 0) { mbar_init(mb0); mbar_init(mb0 + 8); mbar_init(mb0 + 16); }

    const char* gA  = (const char*)g_xt + ((size_t)e * KBT * CAP + m0) * 128;
    const char* gBg = (const char*)g_wg + (((size_t)e * NBT + nb) * KBT << 13);
    const char* gBu = (const char*)g_wu + (((size_t)e * NBT + nb) * KBT << 13);
    __syncthreads();

    auto fill = [&](int it, int fs) {
        if (tid == 0) {
            uint32_t mb = mb0 + fs * 8;
            uint32_t d = tiles + fs * K4_STG;
            mbar_expect(mb, K4_BYTES);
            bulk_cp(d,         gA  + (size_t)it * (CAP * 128), 16384, mb);
            bulk_cp(d + 16384, gBg + (size_t)it * 8192, 8192, mb);
            bulk_cp(d + 24576, gBu + (size_t)it * 8192, 8192, mb);
        }
    };

    // fragment addressing (swizzled tiles)
    const int r0 = wm * 32 + (lane & 15);
    const uint32_t xa = (uint32_t)((r0 & 7) << 4);
    const uint32_t aBase = (uint32_t)(r0 * 128);
    const int rb0 = (lane & 7) + ((lane >> 4) & 1) * 8;
    const uint32_t xb = (uint32_t)((rb0 & 7) << 4);
    const uint32_t bBase = (uint32_t)((rb0 + wn * 32) * 128);
    uint32_t qa[4], qb[4];
#pragma unroll
    for (int ks = 0; ks < 4; ++ks) {
        qa[ks] = ((uint32_t)((lane >> 4) * 16 + ks * 32)) ^ xa;
        qb[ks] = ((uint32_t)(((lane >> 3) & 1) * 16 + ks * 32)) ^ xb;
    }

    float acc[2][2][4][4] = {};

    const int NIT = KBT;   // 16
    fill(0, 0); fill(1, 1);

    int st = 0, pp = 0, fst = 2;
#pragma unroll 1
    for (int it = 0; it < NIT; ++it) {
        mbar_wait(mb0 + st * 8, (uint32_t)pp);
        if (it + 2 < NIT) fill(it + 2, fst);
        const uint32_t s = tiles + st * K4_STG;
        const uint32_t sA = s + aBase;
        const uint32_t sBg = s + 16384 + bBase;
        const uint32_t sBu = s + 24576 + bBase;
#pragma unroll
        for (int ks = 0; ks < 4; ++ks) {
            uint32_t ah[2][4], bb[2][2][4];
#pragma unroll
            for (int mt = 0; mt < 2; ++mt)
                ldsm4(ah[mt], sA + mt * 2048 + qa[ks]);
#pragma unroll
            for (int np = 0; np < 2; ++np) {
                ldsm4(bb[0][np], sBg + np * 2048 + qb[ks]);
                ldsm4(bb[1][np], sBu + np * 2048 + qb[ks]);
            }
#pragma unroll
            for (int g = 0; g < 2; ++g)
#pragma unroll
                for (int mt = 0; mt < 2; ++mt)
#pragma unroll
                    for (int nt = 0; nt < 4; ++nt) {
                        const uint32_t* bp = &bb[g][nt >> 1][(nt & 1) * 2];
                        mma16(acc[g][mt][nt], ah[mt], bp);
                    }
        }
        __syncthreads();
        if (++st == 3) { st = 0; pp ^= 1; }
        if (++fst == 3) fst = 0;
    }

    // epilogue: silu(g)*u -> g_act (tiled swizzled)
    char* pa = (char*)g_act + ((size_t)e * NBT * CAP) * 128;
    const int n0 = nb * 64;
#pragma unroll
    for (int mt = 0; mt < 2; ++mt)
#pragma unroll
        for (int nt = 0; nt < 4; ++nt) {
            int rbase = m0 + wm * 32 + mt * 16 + gID;
            int col = n0 + wn * 32 + nt * 8 + 2 * t4;
            if (col >= INTER) continue;
            int kb = col >> 6;
            uint32_t cl2 = (uint32_t)((col & 63) * 2);
#pragma unroll
            for (int rq = 0; rq < 2; ++rq) {
                int row = rbase + rq * 8;
                float g0 = acc[0][mt][nt][rq * 2],     u0 = acc[1][mt][nt][rq * 2];
                float g1 = acc[0][mt][nt][rq * 2 + 1], u1 = acc[1][mt][nt][rq * 2 + 1];
                float a0 = __fdividef(g0, 1.0f + __expf(-g0)) * u0;
                float a1 = __fdividef(g1, 1.0f + __expf(-g1)) * u1;
                ushort_t h0 = f2h(a0), h1 = f2h(a1);
                size_t off = ((size_t)kb * CAP + row) * 128 +
                             (cl2 ^ (uint32_t)((row & 7) << 4));
                *(uint32_t*)(pa + off) = (uint32_t)h0 | ((uint32_t)h1 << 16);
            }
        }
}

// ---------------- kernel 5: down GEMM (fp16) + scatter ----------------------
#define K5_STG   24576          // A 16KB + B 8KB
#define K5_BYTES 24576
__global__ __launch_bounds__(256, 2) void k5_gemm2(float* __restrict__ out) {
    extern __shared__ char sm[];
    const uint32_t base = saddr(sm);
    const uint32_t mb0 = base;          // 4 mbarriers
    const uint32_t tiles = base + 128;
    const int e = blockIdx.z, m0 = blockIdx.x * 128, nb = blockIdx.y;
    const int tid = threadIdx.x, warp = tid >> 5, lane = tid & 31;
    const int wm = warp >> 1, wn = warp & 1;
    const int gID = lane >> 2, t4 = lane & 3;

    if (tid == 0) {
        mbar_init(mb0); mbar_init(mb0 + 8); mbar_init(mb0 + 16); mbar_init(mb0 + 24);
    }

    const char* gA = (const char*)g_act + ((size_t)e * NBT * CAP + m0) * 128;
    const char* gB = (const char*)g_wd + (((size_t)e * KBT + nb) * NBT << 13);
    __syncthreads();

    auto fill = [&](int it, int fs) {
        if (tid == 0) {
            uint32_t mb = mb0 + fs * 8;
            uint32_t d = tiles + fs * K5_STG;
            mbar_expect(mb, K5_BYTES);
            bulk_cp(d,         gA + (size_t)it * (CAP * 128), 16384, mb);
            bulk_cp(d + 16384, gB + (size_t)it * 8192, 8192, mb);
        }
    };

    const int r0 = wm * 32 + (lane & 15);
    const uint32_t xa = (uint32_t)((r0 & 7) << 4);
    const uint32_t aBase = (uint32_t)(r0 * 128);
    const int rb0 = (lane & 7) + ((lane >> 4) & 1) * 8;
    const uint32_t xb = (uint32_t)((rb0 & 7) << 4);
    const uint32_t bBase = (uint32_t)((rb0 + wn * 32) * 128);
    uint32_t qa[4], qb[4];
#pragma unroll
    for (int ks = 0; ks < 4; ++ks) {
        qa[ks] = ((uint32_t)((lane >> 4) * 16 + ks * 32)) ^ xa;
        qb[ks] = ((uint32_t)(((lane >> 3) & 1) * 16 + ks * 32)) ^ xb;
    }

    float acc[2][4][4] = {};

    const int NIT = NBT;   // 43
    fill(0, 0); fill(1, 1); fill(2, 2);

#pragma unroll 1
    for (int it = 0; it < NIT; ++it) {
        const int st = it & 3;
        mbar_wait(mb0 + st * 8, (uint32_t)((it >> 2) & 1));
        if (it + 3 < NIT) fill(it + 3, (it + 3) & 3);
        const uint32_t s = tiles + st * K5_STG;
        const uint32_t sA = s + aBase;
        const uint32_t sB = s + 16384 + bBase;
#pragma unroll
        for (int ks = 0; ks < 4; ++ks) {
            uint32_t ah[2][4], bb[2][4];
#pragma unroll
            for (int mt = 0; mt < 2; ++mt)
                ldsm4(ah[mt], sA + mt * 2048 + qa[ks]);
#pragma unroll
            for (int np = 0; np < 2; ++np)
                ldsm4(bb[np], sB + np * 2048 + qb[ks]);
#pragma unroll
            for (int mt = 0; mt < 2; ++mt)
#pragma unroll
                for (int nt = 0; nt < 4; ++nt) {
                    const uint32_t* bp = &bb[nt >> 1][(nt & 1) * 2];
                    mma16(acc[mt][nt], ah[mt], bp);
                }
        }
        __syncthreads();
    }

    // epilogue: scale by routing weight, atomic scatter
    const int n0 = nb * 64;
#pragma unroll
    for (int mt = 0; mt < 2; ++mt)
#pragma unroll
        for (int rq = 0; rq < 2; ++rq) {
            int row = m0 + wm * 32 + mt * 16 + gID + rq * 8;
            float w = g_w[e][row];
            if (w == 0.0f) continue;
            int tok = g_tok[e][row];
            float* orow = out + (size_t)tok * CDIM;
#pragma unroll
            for (int nt = 0; nt < 4; ++nt) {
                int col = n0 + wn * 32 + nt * 8 + 2 * t4;
                atomicAdd(&orow[col],     acc[mt][nt][rq * 2 + 0] * w);
                atomicAdd(&orow[col + 1], acc[mt][nt][rq * 2 + 1] * w);
            }
        }
}

// ---------------- launch ----------------
extern "C" void kernel_launch(void* const* d_in, const int* in_sizes, int n_in,
                              void* d_out, int out_size) {
    const float* x    = (const float*)d_in[0];
    const float* cond = (const float*)d_in[1];
    const float* snr  = (const float*)d_in[2];
    const float* gw   = (const float*)d_in[3];
    const float* wgu  = (const float*)d_in[4];
    const float* wd   = (const float*)d_in[5];
    float* out = (float*)d_out;

    const int SM4 = 128 + 3 * K4_STG;   // 98432
    const int SM5 = 128 + 4 * K5_STG;   // 98432
    cudaFuncSetAttribute(k4_gemm1, cudaFuncAttributeMaxDynamicSharedMemorySize, SM4);
    cudaFuncSetAttribute(k5_gemm2, cudaFuncAttributeMaxDynamicSharedMemorySize, SM5);
    cudaFuncSetAttribute(k4_gemm1, cudaFuncAttributePreferredSharedMemoryCarveout, 100);
    cudaFuncSetAttribute(k5_gemm2, cudaFuncAttributePreferredSharedMemoryCarveout, 100);

    kprep<<<NB_TOT, 256>>>(x, cond, snr, gw, wgu, wd, out, out_size);
    k2_select<<<NE, 256>>>();
    k3_compact<<<TK / 256, 256>>>();
    {
        dim3 gg(CAP / 8, NE);
        k3b_gather<<<gg, 256>>>();
    }

    dim3 gg1(CAP / 128, NBT, NE);    // 20 x 43 x 8
    k4_gemm1<<<gg1, 256, SM4>>>();

    dim3 gg2(CAP / 128, KBT, NE);    // 20 x 16 x 8
    k5_gemm2<<<gg2, 256, SM5>>>(out);
}

// round 13
// speedup vs baseline: 1.4817x; 1.0252x over previous
#include <cuda_runtime.h>
#include <cuda_fp16.h>
#include <cstdint>
#include <math.h>

// Problem constants
#define T_TOK 16384
#define TK    32768
#define NE    8
#define CDIM  1024
#define INTER 2730
#define N2    5460
#define CAP   2560
#define NBT   43      // n-tiles for gate/up (2752/64) and k-tiles for down
#define KBT   16      // k-tiles over CDIM

typedef unsigned short ushort_t;

// ---------------- scratch ----------------
__device__ unsigned long long g_key[TK];
__device__ int   g_eid[TK];
__device__ float g_val[TK];
__device__ unsigned long long g_thresh[NE];
__device__ int   g_cnt[NE];
__device__ int   g_tok[NE][CAP];
__device__ float g_w[NE][CAP];

// tiled, pre-swizzled operand storage (tile = 64 rows x 64 halves = 8192 B)
__device__ ushort_t g_wg[(size_t)NE * NBT * KBT * 4096];   // gate  [e][nb][kb]
__device__ ushort_t g_wu[(size_t)NE * NBT * KBT * 4096];   // up    [e][nb][kb]
__device__ ushort_t g_wd[(size_t)NE * KBT * NBT * 4096];   // down  [e][nb][kb]
__device__ ushort_t g_xt[(size_t)NE * KBT * CAP * 64];     // gathered A tiles [e][kb][m][64]
__device__ ushort_t g_act[(size_t)NE * NBT * CAP * 64];    // activations     [e][kb][m][64]

// ---------------- helpers ----------------
__device__ __forceinline__ ushort_t f2h(float f) {
    __half h = __float2half_rn(f);
    return *(ushort_t*)&h;
}
__device__ __forceinline__ uint32_t saddr(const void* p) {
    return (uint32_t)__cvta_generic_to_shared(p);
}
__device__ __forceinline__ void ldsm4(uint32_t* r, uint32_t a) {
    asm volatile("ldmatrix.sync.aligned.m8n8.x4.shared.b16 {%0,%1,%2,%3}, [%4];"
                 : "=r"(r[0]), "=r"(r[1]), "=r"(r[2]), "=r"(r[3]) : "r"(a));
}
__device__ __forceinline__ void mma16(float* c, const uint32_t* a, const uint32_t* b) {
    asm volatile(
        "mma.sync.aligned.m16n8k16.row.col.f32.f16.f16.f32 "
        "{%0,%1,%2,%3},{%4,%5,%6,%7},{%8,%9},{%0,%1,%2,%3};"
        : "+f"(c[0]), "+f"(c[1]), "+f"(c[2]), "+f"(c[3])
        : "r"(a[0]), "r"(a[1]), "r"(a[2]), "r"(a[3]), "r"(b[0]), "r"(b[1]));
}
__device__ __forceinline__ void mbar_init_cnt(uint32_t mb, uint32_t cnt) {
    asm volatile("mbarrier.init.shared.b64 [%0], %1;" :: "r"(mb), "r"(cnt) : "memory");
}
__device__ __forceinline__ void mbar_expect(uint32_t mb, uint32_t bytes) {
    asm volatile("mbarrier.arrive.expect_tx.shared.b64 _, [%0], %1;"
                 :: "r"(mb), "r"(bytes) : "memory");
}
__device__ __forceinline__ void mbar_arrive(uint32_t mb) {
    asm volatile("mbarrier.arrive.shared.b64 _, [%0];" :: "r"(mb) : "memory");
}
__device__ __forceinline__ void mbar_wait(uint32_t mb, uint32_t parity) {
    asm volatile(
        "{\n\t.reg .pred P;\n\tWAIT_%=:\n\t"
        "mbarrier.try_wait.parity.acquire.cta.shared::cta.b64 P, [%0], %1, 0x989680;\n\t"
        "@P bra.uni DONE_%=;\n\tbra.uni WAIT_%=;\n\tDONE_%=:\n\t}"
        :: "r"(mb), "r"(parity) : "memory");
}
__device__ __forceinline__ void bulk_cp(uint32_t dst, const void* src,
                                        uint32_t bytes, uint32_t mb) {
    asm volatile(
        "cp.async.bulk.shared::cta.global.mbarrier::complete_tx::bytes [%0], [%1], %2, [%3];"
        :: "r"(dst), "l"(src), "r"(bytes), "r"(mb) : "memory");
}

// ================== fused prep kernel ==================
#define NB_GU   (171 * 32 * 8)   // 43776
#define NB_DW   (32 * 86 * 8)    // 22016
#define NB_GATE 2048
#define NB_ZERO 1024
#define NB_TOT  (NB_GU + NB_DW + NB_GATE + NB_ZERO)

__global__ __launch_bounds__(256) void kprep(
    const float* __restrict__ x, const float* __restrict__ cond,
    const float* __restrict__ snr, const float* __restrict__ gw,
    const float* __restrict__ wgu, const float* __restrict__ wd,
    float* __restrict__ out, int out_size)
{
    __shared__ float tile[32][33];
    const int bid = blockIdx.x;
    const int tid = threadIdx.x;

    if (bid < NB_GU) {
        // gate_up transpose -> tiled swizzled fp16 (packed pair stores)
        int b = bid;
        int n0 = (b % 171) * 32;
        int k0b = ((b / 171) % 32) * 32;
        int e = b / (171 * 32);
        int tx = tid & 31, ty = tid >> 5;
        for (int i = ty; i < 32; i += 8) {
            int n = n0 + tx, k = k0b + i;
            tile[i][tx] = (n < N2) ? wgu[((size_t)e * CDIM + k) * N2 + n] : 0.0f;
        }
        __syncthreads();
        int kp = tx & 15;
        for (int i = ty * 2 + (tx >> 4); i < 32; i += 16) {
            int n = n0 + i;
            ushort_t h0 = f2h(tile[2 * kp][i]);
            ushort_t h1 = f2h(tile[2 * kp + 1][i]);
            uint32_t v = (uint32_t)h0 | ((uint32_t)h1 << 16);
            char* base;
            int nn;
            if (n < INTER) { base = (char*)g_wg; nn = n; }
            else           { base = (char*)g_wu; nn = n - INTER; }
            int nb = nn >> 6, nl = nn & 63;
            int k = k0b + 2 * kp;
            int kb = k >> 6, kl = k & 63;
            size_t off = ((((size_t)e * NBT + nb) * KBT + kb) << 13)
                       + (size_t)(nl * 128 + ((kl * 2) ^ ((nl & 7) << 4)));
            *(uint32_t*)(base + off) = v;
        }
        return;
    }
    if (bid < NB_GU + NB_DW) {
        // down transpose -> tiled swizzled fp16 (packed pair stores; zero pad)
        int b = bid - NB_GU;
        int n0 = (b % 32) * 32;
        int k0b = ((b / 32) % 86) * 32;
        int e = b / (32 * 86);
        int tx = tid & 31, ty = tid >> 5;
        for (int i = ty; i < 32; i += 8) {
            int k = k0b + i;
            tile[i][tx] = (k < INTER) ? wd[((size_t)e * INTER + k) * CDIM + n0 + tx] : 0.0f;
        }
        __syncthreads();
        int kp = tx & 15;
        for (int i = ty * 2 + (tx >> 4); i < 32; i += 16) {
            int n = n0 + i;
            ushort_t h0 = f2h(tile[2 * kp][i]);
            ushort_t h1 = f2h(tile[2 * kp + 1][i]);
            uint32_t v = (uint32_t)h0 | ((uint32_t)h1 << 16);
            int nb = n >> 6, nl = n & 63;
            int k = k0b + 2 * kp;
            int kb = k >> 6, kl = k & 63;
            size_t off = ((((size_t)e * KBT + nb) * NBT + kb) << 13)
                       + (size_t)(nl * 128 + ((kl * 2) ^ ((nl & 7) << 4)));
            *(uint32_t*)((char*)g_wd + off) = v;
        }
        return;
    }
    if (bid < NB_GU + NB_DW + NB_GATE) {
        // gating: one warp per token
        int b = bid - NB_GU - NB_DW;
        int warp = b * 8 + (tid >> 5);
        int lane = tid & 31;
        int t = warp;
        int bb = t >> 12;

        float acc[NE];
#pragma unroll
        for (int e = 0; e < NE; ++e) acc[e] = 0.0f;

        const float* xr = x + (size_t)t * CDIM;
        const float* cr = cond + (size_t)bb * CDIM;
        for (int d = lane; d < 2 * CDIM; d += 32) {
            float v = (d < CDIM) ? xr[d] : cr[d - CDIM];
            const float* wrow = gw + (size_t)d * NE;
#pragma unroll
            for (int e = 0; e < NE; ++e) acc[e] += v * wrow[e];
        }
#pragma unroll
        for (int e = 0; e < NE; ++e) {
#pragma unroll
            for (int o = 16; o > 0; o >>= 1)
                acc[e] += __shfl_xor_sync(0xFFFFFFFFu, acc[e], o);
        }

        if (lane == 0) {
            bool hn = snr[bb] < 0.5f;
            float lg[NE];
#pragma unroll
            for (int e = 0; e < NE; ++e)
                lg[e] = (hn && e >= 2) ? -INFINITY : acc[e];

            float mx = lg[0];
#pragma unroll
            for (int e = 1; e < NE; ++e) mx = fmaxf(mx, lg[e]);
            float p[NE], s = 0.0f;
#pragma unroll
            for (int e = 0; e < NE; ++e) { p[e] = expf(lg[e] - mx); s += p[e]; }
            float inv = 1.0f / s;
#pragma unroll
            for (int e = 0; e < NE; ++e) p[e] *= inv;

            int i0 = 0; float p0 = p[0];
#pragma unroll
            for (int e = 1; e < NE; ++e) if (p[e] > p0) { p0 = p[e]; i0 = e; }
            int i1 = -1; float p1 = -1.0f;
#pragma unroll
            for (int e = 0; e < NE; ++e) if (e != i0 && p[e] > p1) { p1 = p[e]; i1 = e; }

            float denom = fmaxf(p0 + p1, 1e-12f);
            float w0 = p0 / denom, w1 = p1 / denom;

            int s0 = t * 2, s1 = t * 2 + 1;
            g_eid[s0] = i0; g_val[s0] = w0;
            g_key[s0] = ((unsigned long long)__float_as_uint(w0) << 32) |
                        (unsigned long long)(0xFFFFFFFFu - (unsigned)s0);
            g_eid[s1] = i1; g_val[s1] = w1;
            g_key[s1] = ((unsigned long long)__float_as_uint(w1) << 32) |
                        (unsigned long long)(0xFFFFFFFFu - (unsigned)s1);
        }
        return;
    }
    {
        // zero out + init routing state
        int b = bid - NB_GU - NB_DW - NB_GATE;
        int i = b * 256 + tid;
        int stride = NB_ZERO * 256;
        for (int j = i; j < out_size; j += stride) out[j] = 0.0f;
        if (i < NE) g_cnt[i] = 0;
        for (int j = i; j < NE * CAP; j += stride) {
            ((int*)g_tok)[j] = 0;
            ((float*)g_w)[j] = 0.0f;
        }
    }
}

// ---------------- kernel 2: per-expert exact radix select ----------------
__global__ void k2_select() {
    int e = blockIdx.x;
    int tid = threadIdx.x;
    __shared__ int hist[256];
    __shared__ unsigned long long sh_prefix;
    __shared__ int sh_rem;
    __shared__ int sh_n;

    int cnt = 0;
    for (int s = tid; s < TK; s += 256) if (g_eid[s] == e) cnt++;
    if (tid == 0) sh_n = 0;
    __syncthreads();
    atomicAdd(&sh_n, cnt);
    __syncthreads();
    int n = sh_n;

    if (n <= CAP) {
        if (tid == 0) g_thresh[e] = 0ULL;
        return;
    }

    if (tid == 0) { sh_prefix = 0ULL; sh_rem = CAP; }
    __syncthreads();

    for (int p = 7; p >= 0; --p) {
        if (tid < 256) hist[tid] = 0;
        __syncthreads();
        unsigned long long prefix = sh_prefix;
        int shift_lo = p * 8;
        for (int s = tid; s < TK; s += 256) {
            if (g_eid[s] != e) continue;
            unsigned long long key = g_key[s];
            bool match = (p == 7) || (((key ^ prefix) >> ((p + 1) * 8)) == 0ULL);
            if (match)
                atomicAdd(&hist[(int)((key >> shift_lo) & 255ULL)], 1);
        }
        __syncthreads();
        if (tid == 0) {
            int rem = sh_rem;
            int cum = 0, d = 255;
            for (; d > 0; --d) { cum += hist[d]; if (cum >= rem) break; }
            if (cum < rem) cum += hist[0];
            sh_prefix |= ((unsigned long long)d) << shift_lo;
            sh_rem = rem - (cum - hist[d]);
        }
        __syncthreads();
    }
    if (tid == 0) g_thresh[e] = sh_prefix;
}

// ---------------- kernel 3: compaction ----------------
__global__ void k3_compact() {
    int s = blockIdx.x * blockDim.x + threadIdx.x;
    if (s >= TK) return;
    int e = g_eid[s];
    if (g_key[s] >= g_thresh[e]) {
        int pos = atomicAdd(&g_cnt[e], 1);
        if (pos < CAP) {
            g_tok[e][pos] = s >> 1;
            g_w[e][pos] = g_val[s];
        }
    }
}

// ---------------- kernel 3b: gather + convert x rows into swizzled A tiles --
__global__ __launch_bounds__(256) void k3b_gather(const float* __restrict__ x) {
    const int e = blockIdx.y;
    const int m = blockIdx.x * 8 + (threadIdx.x >> 5);
    const int lane = threadIdx.x & 31;
    const int tok = g_tok[e][m];
    const float4* src = (const float4*)(x + (size_t)tok * CDIM);
    char* dstb = (char*)g_xt + ((size_t)e * KBT * CAP) * 128;
    const uint32_t xr = (uint32_t)((m & 7) << 4);
#pragma unroll
    for (int q = 0; q < 4; ++q) {
        int c = lane + q * 32;               // 16B (8-half) chunk index 0..127
        float4 a = src[2 * c];
        float4 bsrc = src[2 * c + 1];
        uint4 v;
        v.x = (uint32_t)f2h(a.x)    | ((uint32_t)f2h(a.y)    << 16);
        v.y = (uint32_t)f2h(a.z)    | ((uint32_t)f2h(a.w)    << 16);
        v.z = (uint32_t)f2h(bsrc.x) | ((uint32_t)f2h(bsrc.y) << 16);
        v.w = (uint32_t)f2h(bsrc.z) | ((uint32_t)f2h(bsrc.w) << 16);
        int kb = c >> 3;
        uint32_t cb = (uint32_t)((c & 7) * 16) ^ xr;
        *(uint4*)(dstb + ((size_t)kb * CAP + m) * 128 + cb) = v;
    }
}

// ======== GEMM kernels: tiled bulk-copy, decoupled full/empty pipeline ======

// ---------------- kernel 4: gate_up GEMM (fp16) + SiLU*up -------------------
#define K4_STG   32768          // A 16KB + Bg 8KB + Bu 8KB
#define K4_BYTES 32768
__global__ __launch_bounds__(256, 2) void k4_gemm1() {
    extern __shared__ char sm[];
    const uint32_t base = saddr(sm);
    const uint32_t mbF = base;           // full[3]  @ +0,8,16
    const uint32_t mbE = base + 24;      // empty[3] @ +24,32,40
    const uint32_t tiles = base + 128;
    const int e = blockIdx.z, m0 = blockIdx.x * 128, nb = blockIdx.y;
    const int tid = threadIdx.x, warp = tid >> 5, lane = tid & 31;
    const int wm = warp >> 1, wn = warp & 1;
    const int gID = lane >> 2, t4 = lane & 3;

    if (tid == 0) {
#pragma unroll
        for (int s = 0; s < 3; ++s) {
            mbar_init_cnt(mbF + s * 8, 1);
            mbar_init_cnt(mbE + s * 8, 8);
        }
    }

    const char* gA  = (const char*)g_xt + ((size_t)e * KBT * CAP + m0) * 128;
    const char* gBg = (const char*)g_wg + (((size_t)e * NBT + nb) * KBT << 13);
    const char* gBu = (const char*)g_wu + (((size_t)e * NBT + nb) * KBT << 13);
    __syncthreads();

    auto fill = [&](int it, int fs) {
        uint32_t mb = mbF + fs * 8;
        uint32_t d = tiles + fs * K4_STG;
        mbar_expect(mb, K4_BYTES);
        bulk_cp(d,         gA  + (size_t)it * (CAP * 128), 16384, mb);
        bulk_cp(d + 16384, gBg + (size_t)it * 8192, 8192, mb);
        bulk_cp(d + 24576, gBu + (size_t)it * 8192, 8192, mb);
    };

    // fragment addressing (swizzled tiles)
    const int r0 = wm * 32 + (lane & 15);
    const uint32_t xa = (uint32_t)((r0 & 7) << 4);
    const uint32_t aBase = (uint32_t)(r0 * 128);
    const int rb0 = (lane & 7) + ((lane >> 4) & 1) * 8;
    const uint32_t xb = (uint32_t)((rb0 & 7) << 4);
    const uint32_t bBase = (uint32_t)((rb0 + wn * 32) * 128);
    uint32_t qa[4], qb[4];
#pragma unroll
    for (int ks = 0; ks < 4; ++ks) {
        qa[ks] = ((uint32_t)((lane >> 4) * 16 + ks * 32)) ^ xa;
        qb[ks] = ((uint32_t)(((lane >> 3) & 1) * 16 + ks * 32)) ^ xb;
    }

    float acc[2][2][4][4] = {};

    const int NIT = KBT;   // 16
    if (tid == 0) { fill(0, 0); fill(1, 1); fill(2, 2); }

    int st = 0, ph = 0;
#pragma unroll 1
    for (int it = 0; it < NIT; ++it) {
        mbar_wait(mbF + st * 8, (uint32_t)ph);
        const uint32_t s = tiles + st * K4_STG;
        const uint32_t sA = s + aBase;
        const uint32_t sBg = s + 16384 + bBase;
        const uint32_t sBu = s + 24576 + bBase;
#pragma unroll
        for (int ks = 0; ks < 4; ++ks) {
            uint32_t ah[2][4], bb[2][2][4];
#pragma unroll
            for (int mt = 0; mt < 2; ++mt)
                ldsm4(ah[mt], sA + mt * 2048 + qa[ks]);
#pragma unroll
            for (int np = 0; np < 2; ++np) {
                ldsm4(bb[0][np], sBg + np * 2048 + qb[ks]);
                ldsm4(bb[1][np], sBu + np * 2048 + qb[ks]);
            }
#pragma unroll
            for (int g = 0; g < 2; ++g)
#pragma unroll
                for (int mt = 0; mt < 2; ++mt)
#pragma unroll
                    for (int nt = 0; nt < 4; ++nt) {
                        const uint32_t* bp = &bb[g][nt >> 1][(nt & 1) * 2];
                        mma16(acc[g][mt][nt], ah[mt], bp);
                    }
        }
        if (lane == 0) mbar_arrive(mbE + st * 8);
        if (tid == 0 && it + 3 < NIT) {
            mbar_wait(mbE + st * 8, (uint32_t)ph);
            fill(it + 3, st);
        }
        if (++st == 3) { st = 0; ph ^= 1; }
    }

    // epilogue: silu(g)*u -> g_act (tiled swizzled)
    char* pa = (char*)g_act + ((size_t)e * NBT * CAP) * 128;
    const int n0 = nb * 64;
#pragma unroll
    for (int mt = 0; mt < 2; ++mt)
#pragma unroll
        for (int nt = 0; nt < 4; ++nt) {
            int rbase = m0 + wm * 32 + mt * 16 + gID;
            int col = n0 + wn * 32 + nt * 8 + 2 * t4;
            if (col >= INTER) continue;
            int kb = col >> 6;
            uint32_t cl2 = (uint32_t)((col & 63) * 2);
#pragma unroll
            for (int rq = 0; rq < 2; ++rq) {
                int row = rbase + rq * 8;
                float g0 = acc[0][mt][nt][rq * 2],     u0 = acc[1][mt][nt][rq * 2];
                float g1 = acc[0][mt][nt][rq * 2 + 1], u1 = acc[1][mt][nt][rq * 2 + 1];
                float a0 = __fdividef(g0, 1.0f + __expf(-g0)) * u0;
                float a1 = __fdividef(g1, 1.0f + __expf(-g1)) * u1;
                ushort_t h0 = f2h(a0), h1 = f2h(a1);
                size_t off = ((size_t)kb * CAP + row) * 128 +
                             (cl2 ^ (uint32_t)((row & 7) << 4));
                *(uint32_t*)(pa + off) = (uint32_t)h0 | ((uint32_t)h1 << 16);
            }
        }
}

// ---------------- kernel 5: down GEMM (fp16) + scatter ----------------------
#define K5_STG   24576          // A 16KB + B 8KB
#define K5_BYTES 24576
__global__ __launch_bounds__(256, 2) void k5_gemm2(float* __restrict__ out) {
    extern __shared__ char sm[];
    const uint32_t base = saddr(sm);
    const uint32_t mbF = base;           // full[4]
    const uint32_t mbE = base + 32;      // empty[4]
    const uint32_t tiles = base + 128;
    const int e = blockIdx.z, m0 = blockIdx.x * 128, nb = blockIdx.y;
    const int tid = threadIdx.x, warp = tid >> 5, lane = tid & 31;
    const int wm = warp >> 1, wn = warp & 1;
    const int gID = lane >> 2, t4 = lane & 3;

    if (tid == 0) {
#pragma unroll
        for (int s = 0; s < 4; ++s) {
            mbar_init_cnt(mbF + s * 8, 1);
            mbar_init_cnt(mbE + s * 8, 8);
        }
    }

    const char* gA = (const char*)g_act + ((size_t)e * NBT * CAP + m0) * 128;
    const char* gB = (const char*)g_wd + (((size_t)e * KBT + nb) * NBT << 13);
    __syncthreads();

    auto fill = [&](int it, int fs) {
        uint32_t mb = mbF + fs * 8;
        uint32_t d = tiles + fs * K5_STG;
        mbar_expect(mb, K5_BYTES);
        bulk_cp(d,         gA + (size_t)it * (CAP * 128), 16384, mb);
        bulk_cp(d + 16384, gB + (size_t)it * 8192, 8192, mb);
    };

    const int r0 = wm * 32 + (lane & 15);
    const uint32_t xa = (uint32_t)((r0 & 7) << 4);
    const uint32_t aBase = (uint32_t)(r0 * 128);
    const int rb0 = (lane & 7) + ((lane >> 4) & 1) * 8;
    const uint32_t xb = (uint32_t)((rb0 & 7) << 4);
    const uint32_t bBase = (uint32_t)((rb0 + wn * 32) * 128);
    uint32_t qa[4], qb[4];
#pragma unroll
    for (int ks = 0; ks < 4; ++ks) {
        qa[ks] = ((uint32_t)((lane >> 4) * 16 + ks * 32)) ^ xa;
        qb[ks] = ((uint32_t)(((lane >> 3) & 1) * 16 + ks * 32)) ^ xb;
    }

    float acc[2][4][4] = {};

    const int NIT = NBT;   // 43
    if (tid == 0) { fill(0, 0); fill(1, 1); fill(2, 2); fill(3, 3); }

    int st = 0, ph = 0;
#pragma unroll 1
    for (int it = 0; it < NIT; ++it) {
        mbar_wait(mbF + st * 8, (uint32_t)ph);
        const uint32_t s = tiles + st * K5_STG;
        const uint32_t sA = s + aBase;
        const uint32_t sB = s + 16384 + bBase;
#pragma unroll
        for (int ks = 0; ks < 4; ++ks) {
            uint32_t ah[2][4], bb[2][4];
#pragma unroll
            for (int mt = 0; mt < 2; ++mt)
                ldsm4(ah[mt], sA + mt * 2048 + qa[ks]);
#pragma unroll
            for (int np = 0; np < 2; ++np)
                ldsm4(bb[np], sB + np * 2048 + qb[ks]);
#pragma unroll
            for (int mt = 0; mt < 2; ++mt)
#pragma unroll
                for (int nt = 0; nt < 4; ++nt) {
                    const uint32_t* bp = &bb[nt >> 1][(nt & 1) * 2];
                    mma16(acc[mt][nt], ah[mt], bp);
                }
        }
        if (lane == 0) mbar_arrive(mbE + st * 8);
        if (tid == 0 && it + 4 < NIT) {
            mbar_wait(mbE + st * 8, (uint32_t)ph);
            fill(it + 4, st);
        }
        if (++st == 4) { st = 0; ph ^= 1; }
    }

    // epilogue: scale by routing weight, atomic scatter
    const int n0 = nb * 64;
#pragma unroll
    for (int mt = 0; mt < 2; ++mt)
#pragma unroll
        for (int rq = 0; rq < 2; ++rq) {
            int row = m0 + wm * 32 + mt * 16 + gID + rq * 8;
            float w = g_w[e][row];
            if (w == 0.0f) continue;
            int tok = g_tok[e][row];
            float* orow = out + (size_t)tok * CDIM;
#pragma unroll
            for (int nt = 0; nt < 4; ++nt) {
                int col = n0 + wn * 32 + nt * 8 + 2 * t4;
                atomicAdd(&orow[col],     acc[mt][nt][rq * 2 + 0] * w);
                atomicAdd(&orow[col + 1], acc[mt][nt][rq * 2 + 1] * w);
            }
        }
}

// ---------------- launch ----------------
extern "C" void kernel_launch(void* const* d_in, const int* in_sizes, int n_in,
                              void* d_out, int out_size) {
    const float* x    = (const float*)d_in[0];
    const float* cond = (const float*)d_in[1];
    const float* snr  = (const float*)d_in[2];
    const float* gw   = (const float*)d_in[3];
    const float* wgu  = (const float*)d_in[4];
    const float* wd   = (const float*)d_in[5];
    float* out = (float*)d_out;

    const int SM4 = 128 + 3 * K4_STG;   // 98432
    const int SM5 = 128 + 4 * K5_STG;   // 98432
    cudaFuncSetAttribute(k4_gemm1, cudaFuncAttributeMaxDynamicSharedMemorySize, SM4);
    cudaFuncSetAttribute(k5_gemm2, cudaFuncAttributeMaxDynamicSharedMemorySize, SM5);
    cudaFuncSetAttribute(k4_gemm1, cudaFuncAttributePreferredSharedMemoryCarveout, 100);
    cudaFuncSetAttribute(k5_gemm2, cudaFuncAttributePreferredSharedMemoryCarveout, 100);

    kprep<<<NB_TOT, 256>>>(x, cond, snr, gw, wgu, wd, out, out_size);
    k2_select<<<NE, 256>>>();
    k3_compact<<<TK / 256, 256>>>();
    {
        dim3 gg(CAP / 8, NE);
        k3b_gather<<<gg, 256>>>(x);
    }

    dim3 gg1(CAP / 128, NBT, NE);    // 20 x 43 x 8
    k4_gemm1<<<gg1, 256, SM4>>>();

    dim3 gg2(CAP / 128, KBT, NE);    // 20 x 16 x 8
    k5_gemm2<<<gg2, 256, SM5>>>(out);
}

// round 14
// speedup vs baseline: 1.8301x; 1.2351x over previous
#include <cuda_runtime.h>
#include <cuda_fp16.h>
#include <cstdint>
#include <math.h>

// Problem constants
#define T_TOK 16384
#define TK    32768
#define NE    8
#define CDIM  1024
#define INTER 2730
#define N2    5460
#define CAP   2560
#define NBT   43      // n-tiles for gate/up (2752/64) and k-tiles for down
#define KBT   16      // k-tiles over CDIM

typedef unsigned short ushort_t;

// ---------------- scratch ----------------
__device__ float g_val[TK];
__device__ unsigned long long g_ekey[NE][T_TOK];
__device__ int   g_ecnt[NE];
__device__ unsigned long long g_thresh[NE];
__device__ int   g_cnt[NE];
__device__ int   g_tok[NE][CAP];
__device__ float g_w[NE][CAP];

// tiled, pre-swizzled operand storage (tile = 64 rows x 64 halves = 8192 B)
__device__ ushort_t g_wg[(size_t)NE * NBT * KBT * 4096];   // gate  [e][nb][kb]
__device__ ushort_t g_wu[(size_t)NE * NBT * KBT * 4096];   // up    [e][nb][kb]
__device__ ushort_t g_wd[(size_t)NE * KBT * NBT * 4096];   // down  [e][nb][kb]
__device__ ushort_t g_xt[(size_t)NE * KBT * CAP * 64];     // gathered A tiles
__device__ ushort_t g_act[(size_t)NE * NBT * CAP * 64];    // activations

// ---------------- helpers ----------------
__device__ __forceinline__ ushort_t f2h(float f) {
    __half h = __float2half_rn(f);
    return *(ushort_t*)&h;
}
__device__ __forceinline__ uint32_t saddr(const void* p) {
    return (uint32_t)__cvta_generic_to_shared(p);
}
__device__ __forceinline__ void ldsm4(uint32_t* r, uint32_t a) {
    asm volatile("ldmatrix.sync.aligned.m8n8.x4.shared.b16 {%0,%1,%2,%3}, [%4];"
                 : "=r"(r[0]), "=r"(r[1]), "=r"(r[2]), "=r"(r[3]) : "r"(a));
}
__device__ __forceinline__ void mma16(float* c, const uint32_t* a, const uint32_t* b) {
    asm volatile(
        "mma.sync.aligned.m16n8k16.row.col.f32.f16.f16.f32 "
        "{%0,%1,%2,%3},{%4,%5,%6,%7},{%8,%9},{%0,%1,%2,%3};"
        : "+f"(c[0]), "+f"(c[1]), "+f"(c[2]), "+f"(c[3])
        : "r"(a[0]), "r"(a[1]), "r"(a[2]), "r"(a[3]), "r"(b[0]), "r"(b[1]));
}
__device__ __forceinline__ void mbar_init_cnt(uint32_t mb, uint32_t cnt) {
    asm volatile("mbarrier.init.shared.b64 [%0], %1;" :: "r"(mb), "r"(cnt) : "memory");
}
__device__ __forceinline__ void mbar_expect(uint32_t mb, uint32_t bytes) {
    asm volatile("mbarrier.arrive.expect_tx.shared.b64 _, [%0], %1;"
                 :: "r"(mb), "r"(bytes) : "memory");
}
__device__ __forceinline__ void mbar_arrive(uint32_t mb) {
    asm volatile("mbarrier.arrive.shared.b64 _, [%0];" :: "r"(mb) : "memory");
}
__device__ __forceinline__ void mbar_wait(uint32_t mb, uint32_t parity) {
    asm volatile(
        "{\n\t.reg .pred P;\n\tWAIT_%=:\n\t"
        "mbarrier.try_wait.parity.acquire.cta.shared::cta.b64 P, [%0], %1, 0x989680;\n\t"
        "@P bra.uni DONE_%=;\n\tbra.uni WAIT_%=;\n\tDONE_%=:\n\t}"
        :: "r"(mb), "r"(parity) : "memory");
}
__device__ __forceinline__ void bulk_cp(uint32_t dst, const void* src,
                                        uint32_t bytes, uint32_t mb) {
    asm volatile(
        "cp.async.bulk.shared::cta.global.mbarrier::complete_tx::bytes [%0], [%1], %2, [%3];"
        :: "r"(dst), "l"(src), "r"(bytes), "r"(mb) : "memory");
}

// ================== fused prep kernel ==================
#define NB_GU   (171 * 32 * 8)   // 43776
#define NB_DW   (32 * 86 * 8)    // 22016
#define NB_GATE 2048
#define NB_ZERO 1024
#define NB_TOT  (NB_GU + NB_DW + NB_GATE + NB_ZERO)

__global__ __launch_bounds__(256) void kprep(
    const float* __restrict__ x, const float* __restrict__ cond,
    const float* __restrict__ snr, const float* __restrict__ gw,
    const float* __restrict__ wgu, const float* __restrict__ wd,
    float* __restrict__ out, int out_size)
{
    __shared__ float tile[32][33];
    const int bid = blockIdx.x;
    const int tid = threadIdx.x;

    if (bid < NB_GU) {
        // gate_up transpose -> tiled swizzled fp16 (packed pair stores)
        int b = bid;
        int n0 = (b % 171) * 32;
        int k0b = ((b / 171) % 32) * 32;
        int e = b / (171 * 32);
        int tx = tid & 31, ty = tid >> 5;
        for (int i = ty; i < 32; i += 8) {
            int n = n0 + tx, k = k0b + i;
            tile[i][tx] = (n < N2) ? wgu[((size_t)e * CDIM + k) * N2 + n] : 0.0f;
        }
        __syncthreads();
        int kp = tx & 15;
        for (int i = ty * 2 + (tx >> 4); i < 32; i += 16) {
            int n = n0 + i;
            ushort_t h0 = f2h(tile[2 * kp][i]);
            ushort_t h1 = f2h(tile[2 * kp + 1][i]);
            uint32_t v = (uint32_t)h0 | ((uint32_t)h1 << 16);
            char* base;
            int nn;
            if (n < INTER) { base = (char*)g_wg; nn = n; }
            else           { base = (char*)g_wu; nn = n - INTER; }
            int nb = nn >> 6, nl = nn & 63;
            int k = k0b + 2 * kp;
            int kb = k >> 6, kl = k & 63;
            size_t off = ((((size_t)e * NBT + nb) * KBT + kb) << 13)
                       + (size_t)(nl * 128 + ((kl * 2) ^ ((nl & 7) << 4)));
            *(uint32_t*)(base + off) = v;
        }
        return;
    }
    if (bid < NB_GU + NB_DW) {
        // down transpose -> tiled swizzled fp16 (packed pair stores; zero pad)
        int b = bid - NB_GU;
        int n0 = (b % 32) * 32;
        int k0b = ((b / 32) % 86) * 32;
        int e = b / (32 * 86);
        int tx = tid & 31, ty = tid >> 5;
        for (int i = ty; i < 32; i += 8) {
            int k = k0b + i;
            tile[i][tx] = (k < INTER) ? wd[((size_t)e * INTER + k) * CDIM + n0 + tx] : 0.0f;
        }
        __syncthreads();
        int kp = tx & 15;
        for (int i = ty * 2 + (tx >> 4); i < 32; i += 16) {
            int n = n0 + i;
            ushort_t h0 = f2h(tile[2 * kp][i]);
            ushort_t h1 = f2h(tile[2 * kp + 1][i]);
            uint32_t v = (uint32_t)h0 | ((uint32_t)h1 << 16);
            int nb = n >> 6, nl = n & 63;
            int k = k0b + 2 * kp;
            int kb = k >> 6, kl = k & 63;
            size_t off = ((((size_t)e * KBT + nb) * NBT + kb) << 13)
                       + (size_t)(nl * 128 + ((kl * 2) ^ ((nl & 7) << 4)));
            *(uint32_t*)((char*)g_wd + off) = v;
        }
        return;
    }
    if (bid < NB_GU + NB_DW + NB_GATE) {
        // gating: one warp per token, append keys to per-expert lists
        int b = bid - NB_GU - NB_DW;
        int warp = b * 8 + (tid >> 5);
        int lane = tid & 31;
        int t = warp;
        int bb = t >> 12;

        float acc[NE];
#pragma unroll
        for (int e = 0; e < NE; ++e) acc[e] = 0.0f;

        const float* xr = x + (size_t)t * CDIM;
        const float* cr = cond + (size_t)bb * CDIM;
        for (int d = lane; d < 2 * CDIM; d += 32) {
            float v = (d < CDIM) ? xr[d] : cr[d - CDIM];
            const float* wrow = gw + (size_t)d * NE;
#pragma unroll
            for (int e = 0; e < NE; ++e) acc[e] += v * wrow[e];
        }
#pragma unroll
        for (int e = 0; e < NE; ++e) {
#pragma unroll
            for (int o = 16; o > 0; o >>= 1)
                acc[e] += __shfl_xor_sync(0xFFFFFFFFu, acc[e], o);
        }

        if (lane == 0) {
            bool hn = snr[bb] < 0.5f;
            float lg[NE];
#pragma unroll
            for (int e = 0; e < NE; ++e)
                lg[e] = (hn && e >= 2) ? -INFINITY : acc[e];

            float mx = lg[0];
#pragma unroll
            for (int e = 1; e < NE; ++e) mx = fmaxf(mx, lg[e]);
            float p[NE], s = 0.0f;
#pragma unroll
            for (int e = 0; e < NE; ++e) { p[e] = expf(lg[e] - mx); s += p[e]; }
            float inv = 1.0f / s;
#pragma unroll
            for (int e = 0; e < NE; ++e) p[e] *= inv;

            int i0 = 0; float p0 = p[0];
#pragma unroll
            for (int e = 1; e < NE; ++e) if (p[e] > p0) { p0 = p[e]; i0 = e; }
            int i1 = -1; float p1 = -1.0f;
#pragma unroll
            for (int e = 0; e < NE; ++e) if (e != i0 && p[e] > p1) { p1 = p[e]; i1 = e; }

            float denom = fmaxf(p0 + p1, 1e-12f);
            float w0 = p0 / denom, w1 = p1 / denom;

            int s0 = t * 2, s1 = t * 2 + 1;
            g_val[s0] = w0;
            g_val[s1] = w1;
            unsigned long long k0 = ((unsigned long long)__float_as_uint(w0) << 32) |
                                    (unsigned long long)(0xFFFFFFFFu - (unsigned)s0);
            unsigned long long k1 = ((unsigned long long)__float_as_uint(w1) << 32) |
                                    (unsigned long long)(0xFFFFFFFFu - (unsigned)s1);
            int q0 = atomicAdd(&g_ecnt[i0], 1);
            g_ekey[i0][q0] = k0;
            int q1 = atomicAdd(&g_ecnt[i1], 1);
            g_ekey[i1][q1] = k1;
        }
        return;
    }
    {
        // zero out + init routing state
        int b = bid - NB_GU - NB_DW - NB_GATE;
        int i = b * 256 + tid;
        int stride = NB_ZERO * 256;
        for (int j = i; j < out_size; j += stride) out[j] = 0.0f;
        if (i < NE) { g_cnt[i] = 0; }
        for (int j = i; j < NE * CAP; j += stride) {
            ((int*)g_tok)[j] = 0;
            ((float*)g_w)[j] = 0.0f;
        }
    }
}

// tiny init kernel (must run before kprep's gating appends)
__global__ void k0_cnt() {
    if (threadIdx.x < NE) g_ecnt[threadIdx.x] = 0;
}

// ---------------- kernel 2: per-expert exact radix select ----------------
__global__ void k2_select() {
    int e = blockIdx.x;
    int tid = threadIdx.x;
    __shared__ int hist[256];
    __shared__ unsigned long long sh_prefix;
    __shared__ int sh_rem;

    const int n = g_ecnt[e];
    const unsigned long long* list = g_ekey[e];

    if (n <= CAP) {
        if (tid == 0) g_thresh[e] = 0ULL;
        return;
    }

    if (tid == 0) { sh_prefix = 0ULL; sh_rem = CAP; }
    __syncthreads();

    for (int p = 7; p >= 0; --p) {
        if (tid < 256) hist[tid] = 0;
        __syncthreads();
        unsigned long long prefix = sh_prefix;
        int shift_lo = p * 8;
        for (int s = tid; s < n; s += 256) {
            unsigned long long key = list[s];
            bool match = (p == 7) || (((key ^ prefix) >> ((p + 1) * 8)) == 0ULL);
            if (match)
                atomicAdd(&hist[(int)((key >> shift_lo) & 255ULL)], 1);
        }
        __syncthreads();
        if (tid == 0) {
            int rem = sh_rem;
            int cum = 0, d = 255;
            for (; d > 0; --d) { cum += hist[d]; if (cum >= rem) break; }
            if (cum < rem) cum += hist[0];
            sh_prefix |= ((unsigned long long)d) << shift_lo;
            sh_rem = rem - (cum - hist[d]);
        }
        __syncthreads();
    }
    if (tid == 0) g_thresh[e] = sh_prefix;
}

// ---------------- kernel 3: compaction from per-expert lists ----------------
__global__ void k3_compact() {
    int e = blockIdx.y;
    int i = blockIdx.x * 256 + threadIdx.x;
    if (i >= g_ecnt[e]) return;
    unsigned long long key = g_ekey[e][i];
    if (key >= g_thresh[e]) {
        int pos = atomicAdd(&g_cnt[e], 1);
        if (pos < CAP) {
            unsigned s = 0xFFFFFFFFu - (unsigned)(key & 0xFFFFFFFFULL);
            g_tok[e][pos] = (int)(s >> 1);
            g_w[e][pos] = g_val[s];
        }
    }
}

// ---------------- kernel 3b: gather + convert x rows into swizzled A tiles --
__global__ __launch_bounds__(256) void k3b_gather(const float* __restrict__ x) {
    const int e = blockIdx.y;
    const int m = blockIdx.x * 8 + (threadIdx.x >> 5);
    const int lane = threadIdx.x & 31;
    const int tok = g_tok[e][m];
    const float4* src = (const float4*)(x + (size_t)tok * CDIM);
    char* dstb = (char*)g_xt + ((size_t)e * KBT * CAP) * 128;
    const uint32_t xr = (uint32_t)((m & 7) << 4);
#pragma unroll
    for (int q = 0; q < 4; ++q) {
        int c = lane + q * 32;
        float4 a = src[2 * c];
        float4 bsrc = src[2 * c + 1];
        uint4 v;
        v.x = (uint32_t)f2h(a.x)    | ((uint32_t)f2h(a.y)    << 16);
        v.y = (uint32_t)f2h(a.z)    | ((uint32_t)f2h(a.w)    << 16);
        v.z = (uint32_t)f2h(bsrc.x) | ((uint32_t)f2h(bsrc.y) << 16);
        v.w = (uint32_t)f2h(bsrc.z) | ((uint32_t)f2h(bsrc.w) << 16);
        int kb = c >> 3;
        uint32_t cb = (uint32_t)((c & 7) * 16) ^ xr;
        *(uint4*)(dstb + ((size_t)kb * CAP + m) * 128 + cb) = v;
    }
}

// ======== GEMM kernels: tiled bulk-copy, decoupled full/empty pipeline ======

// ---------------- kernel 4: gate_up GEMM (fp16) + SiLU*up -------------------
#define K4_STG   32768          // A 16KB + Bg 8KB + Bu 8KB
#define K4_BYTES 32768
__global__ __launch_bounds__(256, 2) void k4_gemm1() {
    extern __shared__ char sm[];
    const uint32_t base = saddr(sm);
    const uint32_t mbF = base;
    const uint32_t mbE = base + 24;
    const uint32_t tiles = base + 128;
    const int e = blockIdx.z, m0 = blockIdx.x * 128, nb = blockIdx.y;
    const int tid = threadIdx.x, warp = tid >> 5, lane = tid & 31;
    const int wm = warp >> 1, wn = warp & 1;
    const int gID = lane >> 2, t4 = lane & 3;

    if (tid == 0) {
#pragma unroll
        for (int s = 0; s < 3; ++s) {
            mbar_init_cnt(mbF + s * 8, 1);
            mbar_init_cnt(mbE + s * 8, 8);
        }
    }

    const char* gA  = (const char*)g_xt + ((size_t)e * KBT * CAP + m0) * 128;
    const char* gBg = (const char*)g_wg + (((size_t)e * NBT + nb) * KBT << 13);
    const char* gBu = (const char*)g_wu + (((size_t)e * NBT + nb) * KBT << 13);
    __syncthreads();

    auto fill = [&](int it, int fs) {
        uint32_t mb = mbF + fs * 8;
        uint32_t d = tiles + fs * K4_STG;
        mbar_expect(mb, K4_BYTES);
        bulk_cp(d,         gA  + (size_t)it * (CAP * 128), 16384, mb);
        bulk_cp(d + 16384, gBg + (size_t)it * 8192, 8192, mb);
        bulk_cp(d + 24576, gBu + (size_t)it * 8192, 8192, mb);
    };

    const int r0 = wm * 32 + (lane & 15);
    const uint32_t xa = (uint32_t)((r0 & 7) << 4);
    const uint32_t aBase = (uint32_t)(r0 * 128);
    const int rb0 = (lane & 7) + ((lane >> 4) & 1) * 8;
    const uint32_t xb = (uint32_t)((rb0 & 7) << 4);
    const uint32_t bBase = (uint32_t)((rb0 + wn * 32) * 128);
    uint32_t qa[4], qb[4];
#pragma unroll
    for (int ks = 0; ks < 4; ++ks) {
        qa[ks] = ((uint32_t)((lane >> 4) * 16 + ks * 32)) ^ xa;
        qb[ks] = ((uint32_t)(((lane >> 3) & 1) * 16 + ks * 32)) ^ xb;
    }

    float acc[2][2][4][4] = {};

    const int NIT = KBT;   // 16
    if (tid == 0) { fill(0, 0); fill(1, 1); fill(2, 2); }

    int st = 0, ph = 0;
#pragma unroll 1
    for (int it = 0; it < NIT; ++it) {
        mbar_wait(mbF + st * 8, (uint32_t)ph);
        const uint32_t s = tiles + st * K4_STG;
        const uint32_t sA = s + aBase;
        const uint32_t sBg = s + 16384 + bBase;
        const uint32_t sBu = s + 24576 + bBase;
#pragma unroll
        for (int ks = 0; ks < 4; ++ks) {
            uint32_t ah[2][4], bb[2][2][4];
#pragma unroll
            for (int mt = 0; mt < 2; ++mt)
                ldsm4(ah[mt], sA + mt * 2048 + qa[ks]);
#pragma unroll
            for (int np = 0; np < 2; ++np) {
                ldsm4(bb[0][np], sBg + np * 2048 + qb[ks]);
                ldsm4(bb[1][np], sBu + np * 2048 + qb[ks]);
            }
#pragma unroll
            for (int g = 0; g < 2; ++g)
#pragma unroll
                for (int mt = 0; mt < 2; ++mt)
#pragma unroll
                    for (int nt = 0; nt < 4; ++nt) {
                        const uint32_t* bp = &bb[g][nt >> 1][(nt & 1) * 2];
                        mma16(acc[g][mt][nt], ah[mt], bp);
                    }
        }
        if (lane == 0) mbar_arrive(mbE + st * 8);
        if (tid == 0 && it + 3 < NIT) {
            mbar_wait(mbE + st * 8, (uint32_t)ph);
            fill(it + 3, st);
        }
        if (++st == 3) { st = 0; ph ^= 1; }
    }

    // epilogue: silu(g)*u -> g_act (tiled swizzled)
    char* pa = (char*)g_act + ((size_t)e * NBT * CAP) * 128;
    const int n0 = nb * 64;
#pragma unroll
    for (int mt = 0; mt < 2; ++mt)
#pragma unroll
        for (int nt = 0; nt < 4; ++nt) {
            int rbase = m0 + wm * 32 + mt * 16 + gID;
            int col = n0 + wn * 32 + nt * 8 + 2 * t4;
            if (col >= INTER) continue;
            int kb = col >> 6;
            uint32_t cl2 = (uint32_t)((col & 63) * 2);
#pragma unroll
            for (int rq = 0; rq < 2; ++rq) {
                int row = rbase + rq * 8;
                float g0 = acc[0][mt][nt][rq * 2],     u0 = acc[1][mt][nt][rq * 2];
                float g1 = acc[0][mt][nt][rq * 2 + 1], u1 = acc[1][mt][nt][rq * 2 + 1];
                float a0 = __fdividef(g0, 1.0f + __expf(-g0)) * u0;
                float a1 = __fdividef(g1, 1.0f + __expf(-g1)) * u1;
                ushort_t h0 = f2h(a0), h1 = f2h(a1);
                size_t off = ((size_t)kb * CAP + row) * 128 +
                             (cl2 ^ (uint32_t)((row & 7) << 4));
                *(uint32_t*)(pa + off) = (uint32_t)h0 | ((uint32_t)h1 << 16);
            }
        }
}

// ---------------- kernel 5: down GEMM (fp16), 128x128 tile + scatter --------
#define K5_STG   32768          // A 16KB + B1 8KB + B2 8KB
#define K5_BYTES 32768
__global__ __launch_bounds__(256, 2) void k5_gemm2(float* __restrict__ out) {
    extern __shared__ char sm[];
    const uint32_t base = saddr(sm);
    const uint32_t mbF = base;
    const uint32_t mbE = base + 24;
    const uint32_t tiles = base + 128;
    const int e = blockIdx.z, m0 = blockIdx.x * 128, nb = blockIdx.y;  // nb in [0,8)
    const int tid = threadIdx.x, warp = tid >> 5, lane = tid & 31;
    const int wm = warp >> 2, wn = warp & 3;
    const int gID = lane >> 2, t4 = lane & 3;

    if (tid == 0) {
#pragma unroll
        for (int s = 0; s < 3; ++s) {
            mbar_init_cnt(mbF + s * 8, 1);
            mbar_init_cnt(mbE + s * 8, 8);
        }
    }

    const char* gA  = (const char*)g_act + ((size_t)e * NBT * CAP + m0) * 128;
    const char* gB1 = (const char*)g_wd + (((size_t)e * KBT + 2 * nb)     * NBT << 13);
    const char* gB2 = (const char*)g_wd + (((size_t)e * KBT + 2 * nb + 1) * NBT << 13);
    __syncthreads();

    auto fill = [&](int it, int fs) {
        uint32_t mb = mbF + fs * 8;
        uint32_t d = tiles + fs * K5_STG;
        mbar_expect(mb, K5_BYTES);
        bulk_cp(d,         gA  + (size_t)it * (CAP * 128), 16384, mb);
        bulk_cp(d + 16384, gB1 + (size_t)it * 8192, 8192, mb);
        bulk_cp(d + 24576, gB2 + (size_t)it * 8192, 8192, mb);
    };

    const int r0 = wm * 64 + (lane & 15);
    const uint32_t xa = (uint32_t)((r0 & 7) << 4);
    const uint32_t aBase = (uint32_t)(r0 * 128);
    const int rb0 = (lane & 7) + ((lane >> 4) & 1) * 8;
    const uint32_t xb = (uint32_t)((rb0 & 7) << 4);
    const uint32_t bSel = (wn >> 1) ? 24576u : 16384u;
    const uint32_t bBase = bSel + (uint32_t)(((wn & 1) * 32 + rb0) * 128);
    uint32_t qa[4], qb[4];
#pragma unroll
    for (int ks = 0; ks < 4; ++ks) {
        qa[ks] = ((uint32_t)((lane >> 4) * 16 + ks * 32)) ^ xa;
        qb[ks] = ((uint32_t)(((lane >> 3) & 1) * 16 + ks * 32)) ^ xb;
    }

    float acc[4][4][4] = {};

    const int NIT = NBT;   // 43
    if (tid == 0) { fill(0, 0); fill(1, 1); fill(2, 2); }

    int st = 0, ph = 0;
#pragma unroll 1
    for (int it = 0; it < NIT; ++it) {
        mbar_wait(mbF + st * 8, (uint32_t)ph);
        const uint32_t s = tiles + st * K5_STG;
        const uint32_t sA = s + aBase;
        const uint32_t sB = s + bBase;
#pragma unroll
        for (int ks = 0; ks < 4; ++ks) {
            uint32_t ah[4][4], bb[2][4];
#pragma unroll
            for (int mt = 0; mt < 4; ++mt)
                ldsm4(ah[mt], sA + mt * 2048 + qa[ks]);
#pragma unroll
            for (int np = 0; np < 2; ++np)
                ldsm4(bb[np], sB + np * 2048 + qb[ks]);
#pragma unroll
            for (int mt = 0; mt < 4; ++mt)
#pragma unroll
                for (int nt = 0; nt < 4; ++nt) {
                    const uint32_t* bp = &bb[nt >> 1][(nt & 1) * 2];
                    mma16(acc[mt][nt], ah[mt], bp);
                }
        }
        if (lane == 0) mbar_arrive(mbE + st * 8);
        if (tid == 0 && it + 3 < NIT) {
            mbar_wait(mbE + st * 8, (uint32_t)ph);
            fill(it + 3, st);
        }
        if (++st == 3) { st = 0; ph ^= 1; }
    }

    // epilogue: scale by routing weight, atomic scatter
    const int n0 = nb * 128;
#pragma unroll
    for (int mt = 0; mt < 4; ++mt)
#pragma unroll
        for (int rq = 0; rq < 2; ++rq) {
            int row = m0 + wm * 64 + mt * 16 + gID + rq * 8;
            float w = g_w[e][row];
            if (w == 0.0f) continue;
            int tok = g_tok[e][row];
            float* orow = out + (size_t)tok * CDIM;
#pragma unroll
            for (int nt = 0; nt < 4; ++nt) {
                int col = n0 + wn * 32 + nt * 8 + 2 * t4;
                atomicAdd(&orow[col],     acc[mt][nt][rq * 2 + 0] * w);
                atomicAdd(&orow[col + 1], acc[mt][nt][rq * 2 + 1] * w);
            }
        }
}

// ---------------- launch ----------------
extern "C" void kernel_launch(void* const* d_in, const int* in_sizes, int n_in,
                              void* d_out, int out_size) {
    const float* x    = (const float*)d_in[0];
    const float* cond = (const float*)d_in[1];
    const float* snr  = (const float*)d_in[2];
    const float* gw   = (const float*)d_in[3];
    const float* wgu  = (const float*)d_in[4];
    const float* wd   = (const float*)d_in[5];
    float* out = (float*)d_out;

    const int SM4 = 128 + 3 * K4_STG;   // 98432
    const int SM5 = 128 + 3 * K5_STG;   // 98432
    cudaFuncSetAttribute(k4_gemm1, cudaFuncAttributeMaxDynamicSharedMemorySize, SM4);
    cudaFuncSetAttribute(k5_gemm2, cudaFuncAttributeMaxDynamicSharedMemorySize, SM5);
    cudaFuncSetAttribute(k4_gemm1, cudaFuncAttributePreferredSharedMemoryCarveout, 100);
    cudaFuncSetAttribute(k5_gemm2, cudaFuncAttributePreferredSharedMemoryCarveout, 100);

    k0_cnt<<<1, 32>>>();
    kprep<<<NB_TOT, 256>>>(x, cond, snr, gw, wgu, wd, out, out_size);
    k2_select<<<NE, 256>>>();
    {
        dim3 gg(T_TOK / 256, NE);
        k3_compact<<<gg, 256>>>();
    }
    {
        dim3 gg(CAP / 8, NE);
        k3b_gather<<<gg, 256>>>(x);
    }

    dim3 gg1(CAP / 128, NBT, NE);        // 20 x 43 x 8
    k4_gemm1<<<gg1, 256, SM4>>>();

    dim3 gg2(CAP / 128, CDIM / 128, NE); // 20 x 8 x 8
    k5_gemm2<<<gg2, 256, SM5>>>(out);
}

// round 15
// speedup vs baseline: 1.9572x; 1.0694x over previous
#include <cuda_runtime.h>
#include <cuda_fp16.h>
#include <cstdint>
#include <math.h>

// Problem constants
#define T_TOK 16384
#define TK    32768
#define NE    8
#define CDIM  1024
#define INTER 2730
#define N2    5460
#define CAP   2560
#define NBT   43      // n-tiles for gate/up (2752/64) and k-tiles for down
#define KBT   16      // k-tiles over CDIM

typedef unsigned short ushort_t;

// ---------------- scratch ----------------
__device__ float g_val[TK];
__device__ unsigned long long g_ekey[NE][T_TOK];
__device__ int   g_ecnt[NE];
__device__ int   g_tok[NE][CAP];
__device__ float g_w[NE][CAP];

// tiled, pre-swizzled operand storage (tile = 64 rows x 64 halves = 8192 B)
__device__ ushort_t g_wg[(size_t)NE * NBT * KBT * 4096];   // gate  [e][nb][kb]
__device__ ushort_t g_wu[(size_t)NE * NBT * KBT * 4096];   // up    [e][nb][kb]
__device__ ushort_t g_wd[(size_t)NE * KBT * NBT * 4096];   // down  [e][nb][kb]
__device__ ushort_t g_xt[(size_t)NE * KBT * CAP * 64];     // gathered A tiles
__device__ ushort_t g_act[(size_t)NE * NBT * CAP * 64];    // activations

// ---------------- helpers ----------------
__device__ __forceinline__ ushort_t f2h(float f) {
    __half h = __float2half_rn(f);
    return *(ushort_t*)&h;
}
__device__ __forceinline__ uint32_t saddr(const void* p) {
    return (uint32_t)__cvta_generic_to_shared(p);
}
__device__ __forceinline__ void ldsm4(uint32_t* r, uint32_t a) {
    asm volatile("ldmatrix.sync.aligned.m8n8.x4.shared.b16 {%0,%1,%2,%3}, [%4];"
                 : "=r"(r[0]), "=r"(r[1]), "=r"(r[2]), "=r"(r[3]) : "r"(a));
}
__device__ __forceinline__ void mma16(float* c, const uint32_t* a, const uint32_t* b) {
    asm volatile(
        "mma.sync.aligned.m16n8k16.row.col.f32.f16.f16.f32 "
        "{%0,%1,%2,%3},{%4,%5,%6,%7},{%8,%9},{%0,%1,%2,%3};"
        : "+f"(c[0]), "+f"(c[1]), "+f"(c[2]), "+f"(c[3])
        : "r"(a[0]), "r"(a[1]), "r"(a[2]), "r"(a[3]), "r"(b[0]), "r"(b[1]));
}
__device__ __forceinline__ void mbar_init_cnt(uint32_t mb, uint32_t cnt) {
    asm volatile("mbarrier.init.shared.b64 [%0], %1;" :: "r"(mb), "r"(cnt) : "memory");
}
__device__ __forceinline__ void mbar_expect(uint32_t mb, uint32_t bytes) {
    asm volatile("mbarrier.arrive.expect_tx.shared.b64 _, [%0], %1;"
                 :: "r"(mb), "r"(bytes) : "memory");
}
__device__ __forceinline__ void mbar_arrive(uint32_t mb) {
    asm volatile("mbarrier.arrive.shared.b64 _, [%0];" :: "r"(mb) : "memory");
}
__device__ __forceinline__ void mbar_wait(uint32_t mb, uint32_t parity) {
    asm volatile(
        "{\n\t.reg .pred P;\n\tWAIT_%=:\n\t"
        "mbarrier.try_wait.parity.acquire.cta.shared::cta.b64 P, [%0], %1, 0x989680;\n\t"
        "@P bra.uni DONE_%=;\n\tbra.uni WAIT_%=;\n\tDONE_%=:\n\t}"
        :: "r"(mb), "r"(parity) : "memory");
}
__device__ __forceinline__ void bulk_cp(uint32_t dst, const void* src,
                                        uint32_t bytes, uint32_t mb) {
    asm volatile(
        "cp.async.bulk.shared::cta.global.mbarrier::complete_tx::bytes [%0], [%1], %2, [%3];"
        :: "r"(dst), "l"(src), "r"(bytes), "r"(mb) : "memory");
}

// ================== fused prep kernel ==================
#define NB_GU   (86 * 16 * 8)    // 11008: 64x64 tiles over [5460 n][1024 k]
#define NB_DW   (16 * 43 * 8)    // 5504:  64x64 tiles over [1024 n][2730 k]
#define NB_GATE 2048
#define NB_ZERO 1024
#define NB_TOT  (NB_GU + NB_DW + NB_GATE + NB_ZERO)

__global__ __launch_bounds__(256) void kprep(
    const float* __restrict__ x, const float* __restrict__ cond,
    const float* __restrict__ snr, const float* __restrict__ gw,
    const float* __restrict__ wgu, const float* __restrict__ wd,
    float* __restrict__ out, int out_size)
{
    __shared__ float tile[64][67];
    const int bid = blockIdx.x;
    const int tid = threadIdx.x;

    if (bid < NB_GU) {
        // gate_up transpose: [e][k][5460] -> tiled swizzled fp16 [e][nb][kb]
        int ntile = bid % 86;
        int ktile = (bid / 86) % 16;
        int e = bid / (86 * 16);
        const int n0 = ntile * 64, k0 = ktile * 64;
        const int col4 = tid & 15, rr = tid >> 4;
        const int nbase = n0 + col4 * 4;
        const bool nvalid = (nbase + 3 < N2);
#pragma unroll
        for (int i = 0; i < 4; ++i) {
            int r = rr * 4 + i;
            float4 v = nvalid
                ? *(const float4*)&wgu[((size_t)e * CDIM + k0 + r) * N2 + nbase]
                : make_float4(0.f, 0.f, 0.f, 0.f);
            tile[r][col4 * 4 + 0] = v.x;
            tile[r][col4 * 4 + 1] = v.y;
            tile[r][col4 * 4 + 2] = v.z;
            tile[r][col4 * 4 + 3] = v.w;
        }
        __syncthreads();
        const int nl = tid >> 2, part = tid & 3;
        const int n = n0 + nl;
        if (n < N2) {
            char* basep; int nn;
            if (n < INTER) { basep = (char*)g_wg; nn = n; }
            else           { basep = (char*)g_wu; nn = n - INTER; }
            int nb = nn >> 6, nlo = nn & 63;
            size_t tbase = ((((size_t)e * NBT + nb) * KBT + ktile) << 13)
                         + (size_t)(nlo * 128);
            uint32_t xm = (uint32_t)((nlo & 7) << 4);
#pragma unroll
            for (int j = 0; j < 4; ++j) {
                int kl = part * 16 + j * 4;
                uint2 v;
                v.x = (uint32_t)f2h(tile[kl][nl])     | ((uint32_t)f2h(tile[kl + 1][nl]) << 16);
                v.y = (uint32_t)f2h(tile[kl + 2][nl]) | ((uint32_t)f2h(tile[kl + 3][nl]) << 16);
                uint32_t swz = ((uint32_t)(kl * 2)) ^ xm;
                *(uint2*)(basep + tbase + swz) = v;
            }
        }
        return;
    }
    if (bid < NB_GU + NB_DW) {
        // down transpose: [e][k=2730][n=1024] -> tiled swizzled fp16 [e][nb][kb]
        int b = bid - NB_GU;
        int ntile = b % 16;
        int ktile = (b / 16) % 43;
        int e = b / (16 * 43);
        const int n0 = ntile * 64, k0 = ktile * 64;
        const int col4 = tid & 15, rr = tid >> 4;
#pragma unroll
        for (int i = 0; i < 4; ++i) {
            int r = rr * 4 + i;
            int k = k0 + r;
            float4 v = (k < INTER)
                ? *(const float4*)&wd[((size_t)e * INTER + k) * CDIM + n0 + col4 * 4]
                : make_float4(0.f, 0.f, 0.f, 0.f);
            tile[r][col4 * 4 + 0] = v.x;
            tile[r][col4 * 4 + 1] = v.y;
            tile[r][col4 * 4 + 2] = v.z;
            tile[r][col4 * 4 + 3] = v.w;
        }
        __syncthreads();
        const int nl = tid >> 2, part = tid & 3;
        size_t tbase = ((((size_t)e * KBT + ntile) * NBT + ktile) << 13)
                     + (size_t)(nl * 128);
        uint32_t xm = (uint32_t)((nl & 7) << 4);
#pragma unroll
        for (int j = 0; j < 4; ++j) {
            int kl = part * 16 + j * 4;
            uint2 v;
            v.x = (uint32_t)f2h(tile[kl][nl])     | ((uint32_t)f2h(tile[kl + 1][nl]) << 16);
            v.y = (uint32_t)f2h(tile[kl + 2][nl]) | ((uint32_t)f2h(tile[kl + 3][nl]) << 16);
            uint32_t swz = ((uint32_t)(kl * 2)) ^ xm;
            *(uint2*)((char*)g_wd + tbase + swz) = v;
        }
        return;
    }
    if (bid < NB_GU + NB_DW + NB_GATE) {
        // gating: one warp per token, append keys to per-expert lists
        int b = bid - NB_GU - NB_DW;
        int warp = b * 8 + (tid >> 5);
        int lane = tid & 31;
        int t = warp;
        int bb = t >> 12;

        float acc[NE];
#pragma unroll
        for (int e = 0; e < NE; ++e) acc[e] = 0.0f;

        const float* xr = x + (size_t)t * CDIM;
        const float* cr = cond + (size_t)bb * CDIM;
        for (int d = lane; d < 2 * CDIM; d += 32) {
            float v = (d < CDIM) ? xr[d] : cr[d - CDIM];
            const float* wrow = gw + (size_t)d * NE;
#pragma unroll
            for (int e = 0; e < NE; ++e) acc[e] += v * wrow[e];
        }
#pragma unroll
        for (int e = 0; e < NE; ++e) {
#pragma unroll
            for (int o = 16; o > 0; o >>= 1)
                acc[e] += __shfl_xor_sync(0xFFFFFFFFu, acc[e], o);
        }

        if (lane == 0) {
            bool hn = snr[bb] < 0.5f;
            float lg[NE];
#pragma unroll
            for (int e = 0; e < NE; ++e)
                lg[e] = (hn && e >= 2) ? -INFINITY : acc[e];

            float mx = lg[0];
#pragma unroll
            for (int e = 1; e < NE; ++e) mx = fmaxf(mx, lg[e]);
            float p[NE], s = 0.0f;
#pragma unroll
            for (int e = 0; e < NE; ++e) { p[e] = expf(lg[e] - mx); s += p[e]; }
            float inv = 1.0f / s;
#pragma unroll
            for (int e = 0; e < NE; ++e) p[e] *= inv;

            int i0 = 0; float p0 = p[0];
#pragma unroll
            for (int e = 1; e < NE; ++e) if (p[e] > p0) { p0 = p[e]; i0 = e; }
            int i1 = -1; float p1 = -1.0f;
#pragma unroll
            for (int e = 0; e < NE; ++e) if (e != i0 && p[e] > p1) { p1 = p[e]; i1 = e; }

            float denom = fmaxf(p0 + p1, 1e-12f);
            float w0 = p0 / denom, w1 = p1 / denom;

            int s0 = t * 2, s1 = t * 2 + 1;
            g_val[s0] = w0;
            g_val[s1] = w1;
            unsigned long long k0 = ((unsigned long long)__float_as_uint(w0) << 32) |
                                    (unsigned long long)(0xFFFFFFFFu - (unsigned)s0);
            unsigned long long k1 = ((unsigned long long)__float_as_uint(w1) << 32) |
                                    (unsigned long long)(0xFFFFFFFFu - (unsigned)s1);
            int q0 = atomicAdd(&g_ecnt[i0], 1);
            g_ekey[i0][q0] = k0;
            int q1 = atomicAdd(&g_ecnt[i1], 1);
            g_ekey[i1][q1] = k1;
        }
        return;
    }
    {
        // zero out + pad routing lists
        int b = bid - NB_GU - NB_DW - NB_GATE;
        int i = b * 256 + tid;
        int stride = NB_ZERO * 256;
        for (int j = i; j < out_size; j += stride) out[j] = 0.0f;
        for (int j = i; j < NE * CAP; j += stride) {
            ((int*)g_tok)[j] = 0;
            ((float*)g_w)[j] = 0.0f;
        }
    }
}

// ---------------- kernel 2: per-expert radix select + compaction (fused) ----
__global__ void k2_selcomp() {
    int e = blockIdx.x;
    int tid = threadIdx.x;
    __shared__ int hist[256];
    __shared__ unsigned long long sh_prefix;
    __shared__ int sh_rem;
    __shared__ int sh_pos;

    const int n = g_ecnt[e];
    const unsigned long long* list = g_ekey[e];
    unsigned long long thresh = 0ULL;

    if (n > CAP) {
        if (tid == 0) { sh_prefix = 0ULL; sh_rem = CAP; }
        __syncthreads();
        for (int p = 7; p >= 0; --p) {
            hist[tid] = 0;
            __syncthreads();
            unsigned long long prefix = sh_prefix;
            int shift_lo = p * 8;
            for (int s = tid; s < n; s += 256) {
                unsigned long long key = list[s];
                bool match = (p == 7) || (((key ^ prefix) >> ((p + 1) * 8)) == 0ULL);
                if (match)
                    atomicAdd(&hist[(int)((key >> shift_lo) & 255ULL)], 1);
            }
            __syncthreads();
            if (tid == 0) {
                int rem = sh_rem;
                int cum = 0, d = 255;
                for (; d > 0; --d) { cum += hist[d]; if (cum >= rem) break; }
                if (cum < rem) cum += hist[0];
                sh_prefix |= ((unsigned long long)d) << shift_lo;
                sh_rem = rem - (cum - hist[d]);
            }
            __syncthreads();
        }
        thresh = sh_prefix;
    }

    if (tid == 0) sh_pos = 0;
    __syncthreads();
    for (int s = tid; s < n; s += 256) {
        unsigned long long key = list[s];
        if (key >= thresh) {
            int pos = atomicAdd(&sh_pos, 1);
            if (pos < CAP) {
                unsigned sl = 0xFFFFFFFFu - (unsigned)(key & 0xFFFFFFFFULL);
                g_tok[e][pos] = (int)(sl >> 1);
                g_w[e][pos] = g_val[sl];
            }
        }
    }
}

// ---------------- kernel 3b: gather + convert x rows into swizzled A tiles --
__global__ __launch_bounds__(256) void k3b_gather(const float* __restrict__ x) {
    const int e = blockIdx.y;
    const int m = blockIdx.x * 8 + (threadIdx.x >> 5);
    const int lane = threadIdx.x & 31;
    const int tok = g_tok[e][m];
    const float4* src = (const float4*)(x + (size_t)tok * CDIM);
    char* dstb = (char*)g_xt + ((size_t)e * KBT * CAP) * 128;
    const uint32_t xr = (uint32_t)((m & 7) << 4);
#pragma unroll
    for (int q = 0; q < 4; ++q) {
        int c = lane + q * 32;
        float4 a = src[2 * c];
        float4 bsrc = src[2 * c + 1];
        uint4 v;
        v.x = (uint32_t)f2h(a.x)    | ((uint32_t)f2h(a.y)    << 16);
        v.y = (uint32_t)f2h(a.z)    | ((uint32_t)f2h(a.w)    << 16);
        v.z = (uint32_t)f2h(bsrc.x) | ((uint32_t)f2h(bsrc.y) << 16);
        v.w = (uint32_t)f2h(bsrc.z) | ((uint32_t)f2h(bsrc.w) << 16);
        int kb = c >> 3;
        uint32_t cb = (uint32_t)((c & 7) * 16) ^ xr;
        *(uint4*)(dstb + ((size_t)kb * CAP + m) * 128 + cb) = v;
    }
    // reset per-expert counters for the next launch/replay
    if (blockIdx.x == 0 && blockIdx.y == 0 && threadIdx.x < NE)
        g_ecnt[threadIdx.x] = 0;
}

// ======== GEMM kernels: tiled bulk-copy, decoupled full/empty pipeline ======

// ---------------- kernel 4: gate_up GEMM (fp16) + SiLU*up -------------------
#define K4_STG   32768          // A 16KB + Bg 8KB + Bu 8KB
#define K4_BYTES 32768
__global__ __launch_bounds__(256, 2) void k4_gemm1() {
    extern __shared__ char sm[];
    const uint32_t base = saddr(sm);
    const uint32_t mbF = base;
    const uint32_t mbE = base + 24;
    const uint32_t tiles = base + 128;
    const int e = blockIdx.z, m0 = blockIdx.x * 128, nb = blockIdx.y;
    const int tid = threadIdx.x, warp = tid >> 5, lane = tid & 31;
    const int wm = warp >> 1, wn = warp & 1;
    const int gID = lane >> 2, t4 = lane & 3;

    if (tid == 0) {
#pragma unroll
        for (int s = 0; s < 3; ++s) {
            mbar_init_cnt(mbF + s * 8, 1);
            mbar_init_cnt(mbE + s * 8, 8);
        }
    }

    const char* gA  = (const char*)g_xt + ((size_t)e * KBT * CAP + m0) * 128;
    const char* gBg = (const char*)g_wg + (((size_t)e * NBT + nb) * KBT << 13);
    const char* gBu = (const char*)g_wu + (((size_t)e * NBT + nb) * KBT << 13);
    __syncthreads();

    auto fill = [&](int it, int fs) {
        uint32_t mb = mbF + fs * 8;
        uint32_t d = tiles + fs * K4_STG;
        mbar_expect(mb, K4_BYTES);
        bulk_cp(d,         gA  + (size_t)it * (CAP * 128), 16384, mb);
        bulk_cp(d + 16384, gBg + (size_t)it * 8192, 8192, mb);
        bulk_cp(d + 24576, gBu + (size_t)it * 8192, 8192, mb);
    };

    const int r0 = wm * 32 + (lane & 15);
    const uint32_t xa = (uint32_t)((r0 & 7) << 4);
    const uint32_t aBase = (uint32_t)(r0 * 128);
    const int rb0 = (lane & 7) + ((lane >> 4) & 1) * 8;
    const uint32_t xb = (uint32_t)((rb0 & 7) << 4);
    const uint32_t bBase = (uint32_t)((rb0 + wn * 32) * 128);
    uint32_t qa[4], qb[4];
#pragma unroll
    for (int ks = 0; ks < 4; ++ks) {
        qa[ks] = ((uint32_t)((lane >> 4) * 16 + ks * 32)) ^ xa;
        qb[ks] = ((uint32_t)(((lane >> 3) & 1) * 16 + ks * 32)) ^ xb;
    }

    float acc[2][2][4][4] = {};

    const int NIT = KBT;   // 16
    if (tid == 0) { fill(0, 0); fill(1, 1); fill(2, 2); }

    int st = 0, ph = 0;
#pragma unroll 1
    for (int it = 0; it < NIT; ++it) {
        mbar_wait(mbF + st * 8, (uint32_t)ph);
        const uint32_t s = tiles + st * K4_STG;
        const uint32_t sA = s + aBase;
        const uint32_t sBg = s + 16384 + bBase;
        const uint32_t sBu = s + 24576 + bBase;
#pragma unroll
        for (int ks = 0; ks < 4; ++ks) {
            uint32_t ah[2][4], bb[2][2][4];
#pragma unroll
            for (int mt = 0; mt < 2; ++mt)
                ldsm4(ah[mt], sA + mt * 2048 + qa[ks]);
#pragma unroll
            for (int np = 0; np < 2; ++np) {
                ldsm4(bb[0][np], sBg + np * 2048 + qb[ks]);
                ldsm4(bb[1][np], sBu + np * 2048 + qb[ks]);
            }
#pragma unroll
            for (int g = 0; g < 2; ++g)
#pragma unroll
                for (int mt = 0; mt < 2; ++mt)
#pragma unroll
                    for (int nt = 0; nt < 4; ++nt) {
                        const uint32_t* bp = &bb[g][nt >> 1][(nt & 1) * 2];
                        mma16(acc[g][mt][nt], ah[mt], bp);
                    }
        }
        if (lane == 0) mbar_arrive(mbE + st * 8);
        if (tid == 0 && it + 3 < NIT) {
            mbar_wait(mbE + st * 8, (uint32_t)ph);
            fill(it + 3, st);
        }
        if (++st == 3) { st = 0; ph ^= 1; }
    }

    // epilogue: silu(g)*u -> g_act (tiled swizzled)
    char* pa = (char*)g_act + ((size_t)e * NBT * CAP) * 128;
    const int n0 = nb * 64;
#pragma unroll
    for (int mt = 0; mt < 2; ++mt)
#pragma unroll
        for (int nt = 0; nt < 4; ++nt) {
            int rbase = m0 + wm * 32 + mt * 16 + gID;
            int col = n0 + wn * 32 + nt * 8 + 2 * t4;
            if (col >= INTER) continue;
            int kb = col >> 6;
            uint32_t cl2 = (uint32_t)((col & 63) * 2);
#pragma unroll
            for (int rq = 0; rq < 2; ++rq) {
                int row = rbase + rq * 8;
                float g0 = acc[0][mt][nt][rq * 2],     u0 = acc[1][mt][nt][rq * 2];
                float g1 = acc[0][mt][nt][rq * 2 + 1], u1 = acc[1][mt][nt][rq * 2 + 1];
                float a0 = __fdividef(g0, 1.0f + __expf(-g0)) * u0;
                float a1 = __fdividef(g1, 1.0f + __expf(-g1)) * u1;
                ushort_t h0 = f2h(a0), h1 = f2h(a1);
                size_t off = ((size_t)kb * CAP + row) * 128 +
                             (cl2 ^ (uint32_t)((row & 7) << 4));
                *(uint32_t*)(pa + off) = (uint32_t)h0 | ((uint32_t)h1 << 16);
            }
        }
}

// ---------------- kernel 5: down GEMM (fp16), 128x128 tile + scatter --------
#define K5_STG   32768          // A 16KB + B1 8KB + B2 8KB
#define K5_BYTES 32768
__global__ __launch_bounds__(256, 2) void k5_gemm2(float* __restrict__ out) {
    extern __shared__ char sm[];
    const uint32_t base = saddr(sm);
    const uint32_t mbF = base;
    const uint32_t mbE = base + 24;
    const uint32_t tiles = base + 128;
    const int e = blockIdx.z, m0 = blockIdx.x * 128, nb = blockIdx.y;
    const int tid = threadIdx.x, warp = tid >> 5, lane = tid & 31;
    const int wm = warp >> 2, wn = warp & 3;
    const int gID = lane >> 2, t4 = lane & 3;

    if (tid == 0) {
#pragma unroll
        for (int s = 0; s < 3; ++s) {
            mbar_init_cnt(mbF + s * 8, 1);
            mbar_init_cnt(mbE + s * 8, 8);
        }
    }

    const char* gA  = (const char*)g_act + ((size_t)e * NBT * CAP + m0) * 128;
    const char* gB1 = (const char*)g_wd + (((size_t)e * KBT + 2 * nb)     * NBT << 13);
    const char* gB2 = (const char*)g_wd + (((size_t)e * KBT + 2 * nb + 1) * NBT << 13);
    __syncthreads();

    auto fill = [&](int it, int fs) {
        uint32_t mb = mbF + fs * 8;
        uint32_t d = tiles + fs * K5_STG;
        mbar_expect(mb, K5_BYTES);
        bulk_cp(d,         gA  + (size_t)it * (CAP * 128), 16384, mb);
        bulk_cp(d + 16384, gB1 + (size_t)it * 8192, 8192, mb);
        bulk_cp(d + 24576, gB2 + (size_t)it * 8192, 8192, mb);
    };

    const int r0 = wm * 64 + (lane & 15);
    const uint32_t xa = (uint32_t)((r0 & 7) << 4);
    const uint32_t aBase = (uint32_t)(r0 * 128);
    const int rb0 = (lane & 7) + ((lane >> 4) & 1) * 8;
    const uint32_t xb = (uint32_t)((rb0 & 7) << 4);
    const uint32_t bSel = (wn >> 1) ? 24576u : 16384u;
    const uint32_t bBase = bSel + (uint32_t)(((wn & 1) * 32 + rb0) * 128);
    uint32_t qa[4], qb[4];
#pragma unroll
    for (int ks = 0; ks < 4; ++ks) {
        qa[ks] = ((uint32_t)((lane >> 4) * 16 + ks * 32)) ^ xa;
        qb[ks] = ((uint32_t)(((lane >> 3) & 1) * 16 + ks * 32)) ^ xb;
    }

    float acc[4][4][4] = {};

    const int NIT = NBT;   // 43
    if (tid == 0) { fill(0, 0); fill(1, 1); fill(2, 2); }

    int st = 0, ph = 0;
#pragma unroll 1
    for (int it = 0; it < NIT; ++it) {
        mbar_wait(mbF + st * 8, (uint32_t)ph);
        const uint32_t s = tiles + st * K5_STG;
        const uint32_t sA = s + aBase;
        const uint32_t sB = s + bBase;
#pragma unroll
        for (int ks = 0; ks < 4; ++ks) {
            uint32_t ah[4][4], bb[2][4];
#pragma unroll
            for (int mt = 0; mt < 4; ++mt)
                ldsm4(ah[mt], sA + mt * 2048 + qa[ks]);
#pragma unroll
            for (int np = 0; np < 2; ++np)
                ldsm4(bb[np], sB + np * 2048 + qb[ks]);
#pragma unroll
            for (int mt = 0; mt < 4; ++mt)
#pragma unroll
                for (int nt = 0; nt < 4; ++nt) {
                    const uint32_t* bp = &bb[nt >> 1][(nt & 1) * 2];
                    mma16(acc[mt][nt], ah[mt], bp);
                }
        }
        if (lane == 0) mbar_arrive(mbE + st * 8);
        if (tid == 0 && it + 3 < NIT) {
            mbar_wait(mbE + st * 8, (uint32_t)ph);
            fill(it + 3, st);
        }
        if (++st == 3) { st = 0; ph ^= 1; }
    }

    // epilogue: scale by routing weight, atomic scatter
    const int n0 = nb * 128;
#pragma unroll
    for (int mt = 0; mt < 4; ++mt)
#pragma unroll
        for (int rq = 0; rq < 2; ++rq) {
            int row = m0 + wm * 64 + mt * 16 + gID + rq * 8;
            float w = g_w[e][row];
            if (w == 0.0f) continue;
            int tok = g_tok[e][row];
            float* orow = out + (size_t)tok * CDIM;
#pragma unroll
            for (int nt = 0; nt < 4; ++nt) {
                int col = n0 + wn * 32 + nt * 8 + 2 * t4;
                atomicAdd(&orow[col],     acc[mt][nt][rq * 2 + 0] * w);
                atomicAdd(&orow[col + 1], acc[mt][nt][rq * 2 + 1] * w);
            }
        }
}

// ---------------- launch ----------------
extern "C" void kernel_launch(void* const* d_in, const int* in_sizes, int n_in,
                              void* d_out, int out_size) {
    const float* x    = (const float*)d_in[0];
    const float* cond = (const float*)d_in[1];
    const float* snr  = (const float*)d_in[2];
    const float* gw   = (const float*)d_in[3];
    const float* wgu  = (const float*)d_in[4];
    const float* wd   = (const float*)d_in[5];
    float* out = (float*)d_out;

    const int SM4 = 128 + 3 * K4_STG;   // 98432
    const int SM5 = 128 + 3 * K5_STG;   // 98432
    cudaFuncSetAttribute(k4_gemm1, cudaFuncAttributeMaxDynamicSharedMemorySize, SM4);
    cudaFuncSetAttribute(k5_gemm2, cudaFuncAttributeMaxDynamicSharedMemorySize, SM5);
    cudaFuncSetAttribute(k4_gemm1, cudaFuncAttributePreferredSharedMemoryCarveout, 100);
    cudaFuncSetAttribute(k5_gemm2, cudaFuncAttributePreferredSharedMemoryCarveout, 100);

    kprep<<<NB_TOT, 256>>>(x, cond, snr, gw, wgu, wd, out, out_size);
    k2_selcomp<<<NE, 256>>>();
    {
        dim3 gg(CAP / 8, NE);
        k3b_gather<<<gg, 256>>>(x);
    }

    dim3 gg1(CAP / 128, NBT, NE);        // 20 x 43 x 8
    k4_gemm1<<<gg1, 256, SM4>>>();

    dim3 gg2(CAP / 128, CDIM / 128, NE); // 20 x 8 x 8
    k5_gemm2<<<gg2, 256, SM5>>>(out);
}

// round 17
// speedup vs baseline: 1.9789x; 1.0111x over previous
#include <cuda_runtime.h>
#include <cuda_fp16.h>
#include <cstdint>
#include <math.h>

// Problem constants
#define T_TOK 16384
#define TK    32768
#define NE    8
#define CDIM  1024
#define INTER 2730
#define N2    5460
#define CAP   2560
#define NBT   43
#define KBT   16

typedef unsigned short ushort_t;

// ---------------- scratch ----------------
__device__ float g_val[TK];
__device__ unsigned long long g_ekey[NE][T_TOK];
__device__ int   g_ecnt[NE];
__device__ int   g_tok[NE][CAP];
__device__ float g_w[NE][CAP];
__device__ int   g_tnum[T_TOK];
__device__ int   g_tslot[T_TOK][2];

__device__ ushort_t g_wg[(size_t)NE * NBT * KBT * 4096];
__device__ ushort_t g_wu[(size_t)NE * NBT * KBT * 4096];
__device__ ushort_t g_wd[(size_t)NE * KBT * NBT * 4096];
__device__ ushort_t g_xt[(size_t)NE * KBT * CAP * 64];
__device__ ushort_t g_act[(size_t)NE * NBT * CAP * 64];
__device__ float    g_y[(size_t)NE * CAP * CDIM];   // slot outputs (84 MB)

// ---------------- helpers ----------------
__device__ __forceinline__ ushort_t f2h(float f) {
    __half h = __float2half_rn(f);
    return *(ushort_t*)&h;
}
__device__ __forceinline__ uint32_t saddr(const void* p) {
    return (uint32_t)__cvta_generic_to_shared(p);
}
__device__ __forceinline__ void ldsm4(uint32_t* r, uint32_t a) {
    asm volatile("ldmatrix.sync.aligned.m8n8.x4.shared.b16 {%0,%1,%2,%3}, [%4];"
                 : "=r"(r[0]), "=r"(r[1]), "=r"(r[2]), "=r"(r[3]) : "r"(a));
}
__device__ __forceinline__ void mma16(float* c, const uint32_t* a, const uint32_t* b) {
    asm volatile(
        "mma.sync.aligned.m16n8k16.row.col.f32.f16.f16.f32 "
        "{%0,%1,%2,%3},{%4,%5,%6,%7},{%8,%9},{%0,%1,%2,%3};"
        : "+f"(c[0]), "+f"(c[1]), "+f"(c[2]), "+f"(c[3])
        : "r"(a[0]), "r"(a[1]), "r"(a[2]), "r"(a[3]), "r"(b[0]), "r"(b[1]));
}
__device__ __forceinline__ void mbar_init_cnt(uint32_t mb, uint32_t cnt) {
    asm volatile("mbarrier.init.shared.b64 [%0], %1;" :: "r"(mb), "r"(cnt) : "memory");
}
__device__ __forceinline__ void mbar_expect(uint32_t mb, uint32_t bytes) {
    asm volatile("mbarrier.arrive.expect_tx.shared.b64 _, [%0], %1;"
                 :: "r"(mb), "r"(bytes) : "memory");
}
__device__ __forceinline__ void mbar_arrive(uint32_t mb) {
    asm volatile("mbarrier.arrive.shared.b64 _, [%0];" :: "r"(mb) : "memory");
}
__device__ __forceinline__ void mbar_wait(uint32_t mb, uint32_t parity) {
    asm volatile(
        "{\n\t.reg .pred P;\n\tWAIT_%=:\n\t"
        "mbarrier.try_wait.parity.acquire.cta.shared::cta.b64 P, [%0], %1, 0x989680;\n\t"
        "@P bra.uni DONE_%=;\n\tbra.uni WAIT_%=;\n\tDONE_%=:\n\t}"
        :: "r"(mb), "r"(parity) : "memory");
}
__device__ __forceinline__ void bulk_cp(uint32_t dst, const void* src,
                                        uint32_t bytes, uint32_t mb) {
    asm volatile(
        "cp.async.bulk.shared::cta.global.mbarrier::complete_tx::bytes [%0], [%1], %2, [%3];"
        :: "r"(dst), "l"(src), "r"(bytes), "r"(mb) : "memory");
}

// ================== fused prep kernel ==================
#define NB_GU   (86 * 16 * 8)    // 11008
#define NB_DW   (16 * 43 * 8)    // 5504
#define NB_GATE 2048
#define NB_ZERO 64
#define NB_TOT  (NB_GU + NB_DW + NB_GATE + NB_ZERO)

__global__ __launch_bounds__(256) void kprep(
    const float* __restrict__ x, const float* __restrict__ cond,
    const float* __restrict__ snr, const float* __restrict__ gw,
    const float* __restrict__ wgu, const float* __restrict__ wd)
{
    __shared__ float tile[64][67];
    const int bid = blockIdx.x;
    const int tid = threadIdx.x;

    if (bid < NB_GU) {
        // gate_up transpose: [e][k][5460] -> tiled swizzled fp16 [e][nb][kb]
        int ntile = bid % 86;
        int ktile = (bid / 86) % 16;
        int e = bid / (86 * 16);
        const int n0 = ntile * 64, k0 = ktile * 64;
        const int col4 = tid & 15, rr = tid >> 4;
        const int nbase = n0 + col4 * 4;
        const bool nvalid = (nbase + 3 < N2);
#pragma unroll
        for (int i = 0; i < 4; ++i) {
            int r = rr * 4 + i;
            float4 v = nvalid
                ? *(const float4*)&wgu[((size_t)e * CDIM + k0 + r) * N2 + nbase]
                : make_float4(0.f, 0.f, 0.f, 0.f);
            tile[r][col4 * 4 + 0] = v.x;
            tile[r][col4 * 4 + 1] = v.y;
            tile[r][col4 * 4 + 2] = v.z;
            tile[r][col4 * 4 + 3] = v.w;
        }
        __syncthreads();
        const int nl = tid >> 2, part = tid & 3;
        const int n = n0 + nl;
        if (n < N2) {
            char* basep; int nn;
            if (n < INTER) { basep = (char*)g_wg; nn = n; }
            else           { basep = (char*)g_wu; nn = n - INTER; }
            int nb = nn >> 6, nlo = nn & 63;
            size_t tbase = ((((size_t)e * NBT + nb) * KBT + ktile) << 13)
                         + (size_t)(nlo * 128);
            uint32_t xm = (uint32_t)((nlo & 7) << 4);
#pragma unroll
            for (int j = 0; j < 4; ++j) {
                int kl = part * 16 + j * 4;
                uint2 v;
                v.x = (uint32_t)f2h(tile[kl][nl])     | ((uint32_t)f2h(tile[kl + 1][nl]) << 16);
                v.y = (uint32_t)f2h(tile[kl + 2][nl]) | ((uint32_t)f2h(tile[kl + 3][nl]) << 16);
                uint32_t swz = ((uint32_t)(kl * 2)) ^ xm;
                *(uint2*)(basep + tbase + swz) = v;
            }
        }
        return;
    }
    if (bid < NB_GU + NB_DW) {
        // down transpose: [e][k=2730][n=1024] -> tiled swizzled fp16
        int b = bid - NB_GU;
        int ntile = b % 16;
        int ktile = (b / 16) % 43;
        int e = b / (16 * 43);
        const int n0 = ntile * 64, k0 = ktile * 64;
        const int col4 = tid & 15, rr = tid >> 4;
#pragma unroll
        for (int i = 0; i < 4; ++i) {
            int r = rr * 4 + i;
            int k = k0 + r;
            float4 v = (k < INTER)
                ? *(const float4*)&wd[((size_t)e * INTER + k) * CDIM + n0 + col4 * 4]
                : make_float4(0.f, 0.f, 0.f, 0.f);
            tile[r][col4 * 4 + 0] = v.x;
            tile[r][col4 * 4 + 1] = v.y;
            tile[r][col4 * 4 + 2] = v.z;
            tile[r][col4 * 4 + 3] = v.w;
        }
        __syncthreads();
        const int nl = tid >> 2, part = tid & 3;
        size_t tbase = ((((size_t)e * KBT + ntile) * NBT + ktile) << 13)
                     + (size_t)(nl * 128);
        uint32_t xm = (uint32_t)((nl & 7) << 4);
#pragma unroll
        for (int j = 0; j < 4; ++j) {
            int kl = part * 16 + j * 4;
            uint2 v;
            v.x = (uint32_t)f2h(tile[kl][nl])     | ((uint32_t)f2h(tile[kl + 1][nl]) << 16);
            v.y = (uint32_t)f2h(tile[kl + 2][nl]) | ((uint32_t)f2h(tile[kl + 3][nl]) << 16);
            uint32_t swz = ((uint32_t)(kl * 2)) ^ xm;
            *(uint2*)((char*)g_wd + tbase + swz) = v;
        }
        return;
    }
    if (bid < NB_GU + NB_DW + NB_GATE) {
        // gating: one warp per token, append keys to per-expert lists
        int b = bid - NB_GU - NB_DW;
        int warp = b * 8 + (tid >> 5);
        int lane = tid & 31;
        int t = warp;
        int bb = t >> 12;

        float acc[NE];
#pragma unroll
        for (int e = 0; e < NE; ++e) acc[e] = 0.0f;

        const float* xr = x + (size_t)t * CDIM;
        const float* cr = cond + (size_t)bb * CDIM;
        for (int d = lane; d < 2 * CDIM; d += 32) {
            float v = (d < CDIM) ? xr[d] : cr[d - CDIM];
            const float* wrow = gw + (size_t)d * NE;
#pragma unroll
            for (int e = 0; e < NE; ++e) acc[e] += v * wrow[e];
        }
#pragma unroll
        for (int e = 0; e < NE; ++e) {
#pragma unroll
            for (int o = 16; o > 0; o >>= 1)
                acc[e] += __shfl_xor_sync(0xFFFFFFFFu, acc[e], o);
        }

        if (lane == 0) {
            bool hn = snr[bb] < 0.5f;
            float lg[NE];
#pragma unroll
            for (int e = 0; e < NE; ++e)
                lg[e] = (hn && e >= 2) ? -INFINITY : acc[e];

            float mx = lg[0];
#pragma unroll
            for (int e = 1; e < NE; ++e) mx = fmaxf(mx, lg[e]);
            float p[NE], s = 0.0f;
#pragma unroll
            for (int e = 0; e < NE; ++e) { p[e] = expf(lg[e] - mx); s += p[e]; }
            float inv = 1.0f / s;
#pragma unroll
            for (int e = 0; e < NE; ++e) p[e] *= inv;

            int i0 = 0; float p0 = p[0];
#pragma unroll
            for (int e = 1; e < NE; ++e) if (p[e] > p0) { p0 = p[e]; i0 = e; }
            int i1 = -1; float p1 = -1.0f;
#pragma unroll
            for (int e = 0; e < NE; ++e) if (e != i0 && p[e] > p1) { p1 = p[e]; i1 = e; }

            float denom = fmaxf(p0 + p1, 1e-12f);
            float w0 = p0 / denom, w1 = p1 / denom;

            int s0 = t * 2, s1 = t * 2 + 1;
            g_val[s0] = w0;
            g_val[s1] = w1;
            unsigned long long k0 = ((unsigned long long)__float_as_uint(w0) << 32) |
                                    (unsigned long long)(0xFFFFFFFFu - (unsigned)s0);
            unsigned long long k1 = ((unsigned long long)__float_as_uint(w1) << 32) |
                                    (unsigned long long)(0xFFFFFFFFu - (unsigned)s1);
            int q0 = atomicAdd(&g_ecnt[i0], 1);
            g_ekey[i0][q0] = k0;
            int q1 = atomicAdd(&g_ecnt[i1], 1);
            g_ekey[i1][q1] = k1;
        }
        return;
    }
    {
        // reset per-token inverse-map counters
        int b = bid - NB_GU - NB_DW - NB_GATE;
        int i = b * 256 + tid;
        int stride = NB_ZERO * 256;
        for (int j = i; j < T_TOK; j += stride) g_tnum[j] = 0;
    }
}

// ---------------- kernel 2: radix select + compaction + inverse map ---------
__global__ __launch_bounds__(1024) void k2_selcomp() {
    int e = blockIdx.x;
    int tid = threadIdx.x;
    __shared__ int hist[256];
    __shared__ unsigned long long sh_prefix;
    __shared__ int sh_rem;
    __shared__ int sh_pos;

    const int n = g_ecnt[e];
    const unsigned long long* list = g_ekey[e];
    unsigned long long thresh = 0ULL;

    if (n > CAP) {
        if (tid == 0) { sh_prefix = 0ULL; sh_rem = CAP; }
        __syncthreads();
        for (int p = 7; p >= 0; --p) {
            if (tid < 256) hist[tid] = 0;
            __syncthreads();
            unsigned long long prefix = sh_prefix;
            int shift_lo = p * 8;
            for (int s = tid; s < n; s += 1024) {
                unsigned long long key = list[s];
                bool match = (p == 7) || (((key ^ prefix) >> ((p + 1) * 8)) == 0ULL);
                if (match)
                    atomicAdd(&hist[(int)((key >> shift_lo) & 255ULL)], 1);
            }
            __syncthreads();
            if (tid == 0) {
                int rem = sh_rem;
                int cum = 0, d = 255;
                for (; d > 0; --d) { cum += hist[d]; if (cum >= rem) break; }
                if (cum < rem) cum += hist[0];
                sh_prefix |= ((unsigned long long)d) << shift_lo;
                sh_rem = rem - (cum - hist[d]);
            }
            __syncthreads();
        }
        thresh = sh_prefix;
    }

    if (tid == 0) sh_pos = 0;
    __syncthreads();
    for (int s = tid; s < n; s += 1024) {
        unsigned long long key = list[s];
        if (key >= thresh) {
            int pos = atomicAdd(&sh_pos, 1);
            if (pos < CAP) {
                unsigned sl = 0xFFFFFFFFu - (unsigned)(key & 0xFFFFFFFFULL);
                int tok = (int)(sl >> 1);
                g_tok[e][pos] = tok;
                g_w[e][pos] = g_val[sl];
                int q = atomicAdd(&g_tnum[tok], 1);
                g_tslot[tok][q] = (e << 16) | pos;
            }
        }
    }
}

// ---------------- kernel 3b: gather + convert x rows into swizzled A tiles --
__global__ __launch_bounds__(256) void k3b_gather(const float* __restrict__ x) {
    const int e = blockIdx.y;
    const int m = blockIdx.x * 8 + (threadIdx.x >> 5);
    const int lane = threadIdx.x & 31;
    const int tok = g_tok[e][m];
    const float4* src = (const float4*)(x + (size_t)tok * CDIM);
    char* dstb = (char*)g_xt + ((size_t)e * KBT * CAP) * 128;
    const uint32_t xr = (uint32_t)((m & 7) << 4);
#pragma unroll
    for (int q = 0; q < 4; ++q) {
        int c = lane + q * 32;
        float4 a = src[2 * c];
        float4 bsrc = src[2 * c + 1];
        uint4 v;
        v.x = (uint32_t)f2h(a.x)    | ((uint32_t)f2h(a.y)    << 16);
        v.y = (uint32_t)f2h(a.z)    | ((uint32_t)f2h(a.w)    << 16);
        v.z = (uint32_t)f2h(bsrc.x) | ((uint32_t)f2h(bsrc.y) << 16);
        v.w = (uint32_t)f2h(bsrc.z) | ((uint32_t)f2h(bsrc.w) << 16);
        int kb = c >> 3;
        uint32_t cb = (uint32_t)((c & 7) * 16) ^ xr;
        *(uint4*)(dstb + ((size_t)kb * CAP + m) * 128 + cb) = v;
    }
    if (blockIdx.x == 0 && blockIdx.y == 0 && threadIdx.x < NE)
        g_ecnt[threadIdx.x] = 0;
}

// ======== GEMM kernels: tiled bulk-copy, decoupled full/empty pipeline ======

// ---------------- kernel 4: gate_up GEMM (fp16) + SiLU*up -------------------
#define K4_STG   32768
#define K4_BYTES 32768
__global__ __launch_bounds__(256, 2) void k4_gemm1() {
    extern __shared__ char sm[];
    const uint32_t base = saddr(sm);
    const uint32_t mbF = base;
    const uint32_t mbE = base + 24;
    const uint32_t tiles = base + 128;
    const int e = blockIdx.z, m0 = blockIdx.x * 128, nb = blockIdx.y;
    const int tid = threadIdx.x, warp = tid >> 5, lane = tid & 31;
    const int wm = warp >> 1, wn = warp & 1;
    const int gID = lane >> 2, t4 = lane & 3;

    if (tid == 0) {
#pragma unroll
        for (int s = 0; s < 3; ++s) {
            mbar_init_cnt(mbF + s * 8, 1);
            mbar_init_cnt(mbE + s * 8, 8);
        }
    }

    const char* gA  = (const char*)g_xt + ((size_t)e * KBT * CAP + m0) * 128;
    const char* gBg = (const char*)g_wg + (((size_t)e * NBT + nb) * KBT << 13);
    const char* gBu = (const char*)g_wu + (((size_t)e * NBT + nb) * KBT << 13);
    __syncthreads();

    auto fill = [&](int it, int fs) {
        uint32_t mb = mbF + fs * 8;
        uint32_t d = tiles + fs * K4_STG;
        mbar_expect(mb, K4_BYTES);
        bulk_cp(d,         gA  + (size_t)it * (CAP * 128), 16384, mb);
        bulk_cp(d + 16384, gBg + (size_t)it * 8192, 8192, mb);
        bulk_cp(d + 24576, gBu + (size_t)it * 8192, 8192, mb);
    };

    const int r0 = wm * 32 + (lane & 15);
    const uint32_t xa = (uint32_t)((r0 & 7) << 4);
    const uint32_t aBase = (uint32_t)(r0 * 128);
    const int rb0 = (lane & 7) + ((lane >> 4) & 1) * 8;
    const uint32_t xb = (uint32_t)((rb0 & 7) << 4);
    const uint32_t bBase = (uint32_t)((rb0 + wn * 32) * 128);
    uint32_t qa[4], qb[4];
#pragma unroll
    for (int ks = 0; ks < 4; ++ks) {
        qa[ks] = ((uint32_t)((lane >> 4) * 16 + ks * 32)) ^ xa;
        qb[ks] = ((uint32_t)(((lane >> 3) & 1) * 16 + ks * 32)) ^ xb;
    }

    float acc[2][2][4][4] = {};

    const int NIT = KBT;   // 16
    if (tid == 0) { fill(0, 0); fill(1, 1); fill(2, 2); }

    int st = 0, ph = 0;
#pragma unroll 1
    for (int it = 0; it < NIT; ++it) {
        mbar_wait(mbF + st * 8, (uint32_t)ph);
        const uint32_t s = tiles + st * K4_STG;
        const uint32_t sA = s + aBase;
        const uint32_t sBg = s + 16384 + bBase;
        const uint32_t sBu = s + 24576 + bBase;
#pragma unroll
        for (int ks = 0; ks < 4; ++ks) {
            uint32_t ah[2][4], bb[2][2][4];
#pragma unroll
            for (int mt = 0; mt < 2; ++mt)
                ldsm4(ah[mt], sA + mt * 2048 + qa[ks]);
#pragma unroll
            for (int np = 0; np < 2; ++np) {
                ldsm4(bb[0][np], sBg + np * 2048 + qb[ks]);
                ldsm4(bb[1][np], sBu + np * 2048 + qb[ks]);
            }
#pragma unroll
            for (int g = 0; g < 2; ++g)
#pragma unroll
                for (int mt = 0; mt < 2; ++mt)
#pragma unroll
                    for (int nt = 0; nt < 4; ++nt) {
                        const uint32_t* bp = &bb[g][nt >> 1][(nt & 1) * 2];
                        mma16(acc[g][mt][nt], ah[mt], bp);
                    }
        }
        if (lane == 0) mbar_arrive(mbE + st * 8);
        if (tid == 0 && it + 3 < NIT) {
            mbar_wait(mbE + st * 8, (uint32_t)ph);
            fill(it + 3, st);
        }
        if (++st == 3) { st = 0; ph ^= 1; }
    }

    // epilogue: silu(g)*u -> g_act (tiled swizzled)
    char* pa = (char*)g_act + ((size_t)e * NBT * CAP) * 128;
    const int n0 = nb * 64;
#pragma unroll
    for (int mt = 0; mt < 2; ++mt)
#pragma unroll
        for (int nt = 0; nt < 4; ++nt) {
            int rbase = m0 + wm * 32 + mt * 16 + gID;
            int col = n0 + wn * 32 + nt * 8 + 2 * t4;
            if (col >= INTER) continue;
            int kb = col >> 6;
            uint32_t cl2 = (uint32_t)((col & 63) * 2);
#pragma unroll
            for (int rq = 0; rq < 2; ++rq) {
                int row = rbase + rq * 8;
                float g0 = acc[0][mt][nt][rq * 2],     u0 = acc[1][mt][nt][rq * 2];
                float g1 = acc[0][mt][nt][rq * 2 + 1], u1 = acc[1][mt][nt][rq * 2 + 1];
                float a0 = __fdividef(g0, 1.0f + __expf(-g0)) * u0;
                float a1 = __fdividef(g1, 1.0f + __expf(-g1)) * u1;
                ushort_t h0 = f2h(a0), h1 = f2h(a1);
                size_t off = ((size_t)kb * CAP + row) * 128 +
                             (cl2 ^ (uint32_t)((row & 7) << 4));
                *(uint32_t*)(pa + off) = (uint32_t)h0 | ((uint32_t)h1 << 16);
            }
        }
}

// ---------------- kernel 5: down GEMM (fp16), 128x128 tile, slot store ------
#define K5_STG   32768
#define K5_BYTES 32768
__global__ __launch_bounds__(256, 2) void k5_gemm2() {
    extern __shared__ char sm[];
    const uint32_t base = saddr(sm);
    const uint32_t mbF = base;
    const uint32_t mbE = base + 24;
    const uint32_t tiles = base + 128;
    const int e = blockIdx.z, m0 = blockIdx.x * 128, nb = blockIdx.y;
    const int tid = threadIdx.x, warp = tid >> 5, lane = tid & 31;
    const int wm = warp >> 2, wn = warp & 3;
    const int gID = lane >> 2, t4 = lane & 3;

    if (tid == 0) {
#pragma unroll
        for (int s = 0; s < 3; ++s) {
            mbar_init_cnt(mbF + s * 8, 1);
            mbar_init_cnt(mbE + s * 8, 8);
        }
    }

    const char* gA  = (const char*)g_act + ((size_t)e * NBT * CAP + m0) * 128;
    const char* gB1 = (const char*)g_wd + (((size_t)e * KBT + 2 * nb)     * NBT << 13);
    const char* gB2 = (const char*)g_wd + (((size_t)e * KBT + 2 * nb + 1) * NBT << 13);
    __syncthreads();

    auto fill = [&](int it, int fs) {
        uint32_t mb = mbF + fs * 8;
        uint32_t d = tiles + fs * K5_STG;
        mbar_expect(mb, K5_BYTES);
        bulk_cp(d,         gA  + (size_t)it * (CAP * 128), 16384, mb);
        bulk_cp(d + 16384, gB1 + (size_t)it * 8192, 8192, mb);
        bulk_cp(d + 24576, gB2 + (size_t)it * 8192, 8192, mb);
    };

    const int r0 = wm * 64 + (lane & 15);
    const uint32_t xa = (uint32_t)((r0 & 7) << 4);
    const uint32_t aBase = (uint32_t)(r0 * 128);
    const int rb0 = (lane & 7) + ((lane >> 4) & 1) * 8;
    const uint32_t xb = (uint32_t)((rb0 & 7) << 4);
    const uint32_t bSel = (wn >> 1) ? 24576u : 16384u;
    const uint32_t bBase = bSel + (uint32_t)(((wn & 1) * 32 + rb0) * 128);
    uint32_t qa[4], qb[4];
#pragma unroll
    for (int ks = 0; ks < 4; ++ks) {
        qa[ks] = ((uint32_t)((lane >> 4) * 16 + ks * 32)) ^ xa;
        qb[ks] = ((uint32_t)(((lane >> 3) & 1) * 16 + ks * 32)) ^ xb;
    }

    float acc[4][4][4] = {};

    const int NIT = NBT;   // 43
    if (tid == 0) { fill(0, 0); fill(1, 1); fill(2, 2); }

    int st = 0, ph = 0;
#pragma unroll 1
    for (int it = 0; it < NIT; ++it) {
        mbar_wait(mbF + st * 8, (uint32_t)ph);
        const uint32_t s = tiles + st * K5_STG;
        const uint32_t sA = s + aBase;
        const uint32_t sB = s + bBase;
#pragma unroll
        for (int ks = 0; ks < 4; ++ks) {
            uint32_t ah[4][4], bb[2][4];
#pragma unroll
            for (int mt = 0; mt < 4; ++mt)
                ldsm4(ah[mt], sA + mt * 2048 + qa[ks]);
#pragma unroll
            for (int np = 0; np < 2; ++np)
                ldsm4(bb[np], sB + np * 2048 + qb[ks]);
#pragma unroll
            for (int mt = 0; mt < 4; ++mt)
#pragma unroll
                for (int nt = 0; nt < 4; ++nt) {
                    const uint32_t* bp = &bb[nt >> 1][(nt & 1) * 2];
                    mma16(acc[mt][nt], ah[mt], bp);
                }
        }
        if (lane == 0) mbar_arrive(mbE + st * 8);
        if (tid == 0 && it + 3 < NIT) {
            mbar_wait(mbE + st * 8, (uint32_t)ph);
            fill(it + 3, st);
        }
        if (++st == 3) { st = 0; ph ^= 1; }
    }

    // epilogue: plain coalesced float2 stores to slot-output buffer
    const int n0 = nb * 128;
#pragma unroll
    for (int mt = 0; mt < 4; ++mt)
#pragma unroll
        for (int rq = 0; rq < 2; ++rq) {
            int row = m0 + wm * 64 + mt * 16 + gID + rq * 8;
            float* yrow = g_y + ((size_t)e * CAP + row) * CDIM;
#pragma unroll
            for (int nt = 0; nt < 4; ++nt) {
                int col = n0 + wn * 32 + nt * 8 + 2 * t4;
                *(float2*)(yrow + col) =
                    make_float2(acc[mt][nt][rq * 2], acc[mt][nt][rq * 2 + 1]);
            }
        }
}

// ---------------- kernel 6: combine slot outputs -> out ---------------------
__global__ __launch_bounds__(256) void k6_combine(float* __restrict__ out, int out_size) {
    const int t = blockIdx.x * 8 + (threadIdx.x >> 5);
    const int lane = threadIdx.x & 31;

    // zero any tail outputs (e.g., the scalar aux-loss) every call
    if (blockIdx.x == 0 && threadIdx.x == 0) {
        for (int j = T_TOK * CDIM; j < out_size; ++j) out[j] = 0.0f;
    }

    const int ne = g_tnum[t];
    float w0 = 0.0f, w1 = 0.0f;
    const float* y0 = g_y;
    const float* y1 = g_y;
    if (ne > 0) {
        int s = g_tslot[t][0];
        int e = s >> 16, pos = s & 0xFFFF;
        w0 = g_w[e][pos];
        y0 = g_y + ((size_t)e * CAP + pos) * CDIM;
    }
    if (ne > 1) {
        int s = g_tslot[t][1];
        int e = s >> 16, pos = s & 0xFFFF;
        w1 = g_w[e][pos];
        y1 = g_y + ((size_t)e * CAP + pos) * CDIM;
    }
    float* orow = out + (size_t)t * CDIM;
#pragma unroll
    for (int c = lane * 4; c < CDIM; c += 128) {
        float4 a = *(const float4*)(y0 + c);
        float4 b = *(const float4*)(y1 + c);
        float4 r;
        r.x = w0 * a.x + w1 * b.x;
        r.y = w0 * a.y + w1 * b.y;
        r.z = w0 * a.z + w1 * b.z;
        r.w = w0 * a.w + w1 * b.w;
        *(float4*)(orow + c) = r;
    }
}

// ---------------- launch ----------------
extern "C" void kernel_launch(void* const* d_in, const int* in_sizes, int n_in,
                              void* d_out, int out_size) {
    const float* x    = (const float*)d_in[0];
    const float* cond = (const float*)d_in[1];
    const float* snr  = (const float*)d_in[2];
    const float* gw   = (const float*)d_in[3];
    const float* wgu  = (const float*)d_in[4];
    const float* wd   = (const float*)d_in[5];
    float* out = (float*)d_out;

    const int SM4 = 128 + 3 * K4_STG;   // 98432
    const int SM5 = 128 + 3 * K5_STG;   // 98432
    cudaFuncSetAttribute(k4_gemm1, cudaFuncAttributeMaxDynamicSharedMemorySize, SM4);
    cudaFuncSetAttribute(k5_gemm2, cudaFuncAttributeMaxDynamicSharedMemorySize, SM5);
    cudaFuncSetAttribute(k4_gemm1, cudaFuncAttributePreferredSharedMemoryCarveout, 100);
    cudaFuncSetAttribute(k5_gemm2, cudaFuncAttributePreferredSharedMemoryCarveout, 100);

    kprep<<<NB_TOT, 256>>>(x, cond, snr, gw, wgu, wd);
    k2_selcomp<<<NE, 1024>>>();
    {
        dim3 gg(CAP / 8, NE);
        k3b_gather<<<gg, 256>>>(x);
    }

    dim3 gg1(CAP / 128, NBT, NE);        // 20 x 43 x 8
    k4_gemm1<<<gg1, 256, SM4>>>();

    dim3 gg2(CAP / 128, CDIM / 128, NE); // 20 x 8 x 8
    k5_gemm2<<<gg2, 256, SM5>>>();

    k6_combine<<<T_TOK / 8, 256>>>(out, out_size);
}